// round 2
// baseline (speedup 1.0000x reference)
#include <cuda_runtime.h>
#include <math.h>

#define H    128
#define KNB  48
#define PITCH 132   // smem row pitch (floats) to dodge bank conflicts
#define NN_CONST 2048

// ---------------- scratch (no allocs allowed) ----------------
__device__ float g_W1eff[4 * H * H];      // folded W1: [hV_i | hE(x2 folded) | hV_nj | hVa_nj]
__device__ float g_hV1[4096 * H];         // h_V after node-message LN (pre-FFN)

__device__ __forceinline__ float gelu_exact(float x) {
    return 0.5f * x * (1.0f + erff(x * 0.70710678118654752f));
}

// ---------------- smem loaders ----------------
__device__ __forceinline__ void load_W(float* sW, const float* __restrict__ g, int tid) {
    const float4* s = (const float4*)g;
    float4* d = (float4*)sW;
#pragma unroll
    for (int i = tid; i < H * H / 4; i += 128) d[i] = s[i];
}

__device__ __forceinline__ void load_rows(float* sX, const float* __restrict__ src, int tid) {
    // src: KNB contiguous rows of H floats
    for (int i = tid; i < KNB * (H / 4); i += 128) {
        int e = i >> 5, q = i & 31;
        float4 v = ((const float4*)src)[e * (H / 4) + q];
        float* d = sX + e * PITCH + q * 4;
        d[0] = v.x; d[1] = v.y; d[2] = v.z; d[3] = v.w;
    }
}

__device__ __forceinline__ void load_gather(float* sX, const float* __restrict__ base,
                                            const int* sIdx, int tid) {
    for (int i = tid; i < KNB * (H / 4); i += 128) {
        int e = i >> 5, q = i & 31;
        const float4* src = (const float4*)(base + (size_t)sIdx[e] * H);
        float4 v = src[q];
        float* d = sX + e * PITCH + q * 4;
        d[0] = v.x; d[1] = v.y; d[2] = v.z; d[3] = v.w;
    }
}

// ---------------- 48x128 @ 128x128 register-blocked GEMM ----------------
// 128 threads: tn = tid&15 (8 cols each), tm = tid>>4 (6 rows each)
__device__ __forceinline__ void gemm48(const float* __restrict__ sX,
                                       const float* __restrict__ sW,
                                       int tm, int tn, float acc[6][8]) {
    const float* xr0 = sX + (tm * 6 + 0) * PITCH;
    const float* xr1 = sX + (tm * 6 + 1) * PITCH;
    const float* xr2 = sX + (tm * 6 + 2) * PITCH;
    const float* xr3 = sX + (tm * 6 + 3) * PITCH;
    const float* xr4 = sX + (tm * 6 + 4) * PITCH;
    const float* xr5 = sX + (tm * 6 + 5) * PITCH;
#pragma unroll 4
    for (int k = 0; k < H; k++) {
        float a0 = xr0[k], a1 = xr1[k], a2 = xr2[k];
        float a3 = xr3[k], a4 = xr4[k], a5 = xr5[k];
        const float* w = sW + k * H + tn * 8;
        float4 bA = *(const float4*)w;
        float4 bB = *(const float4*)(w + 4);
        float b[8] = {bA.x, bA.y, bA.z, bA.w, bB.x, bB.y, bB.z, bB.w};
#pragma unroll
        for (int i = 0; i < 8; i++) {
            acc[0][i] += a0 * b[i];
            acc[1][i] += a1 * b[i];
            acc[2][i] += a2 * b[i];
            acc[3][i] += a3 * b[i];
            acc[4][i] += a4 * b[i];
            acc[5][i] += a5 * b[i];
        }
    }
}

// ---------------- kernel 0: fold W1 (h_E appears twice in concat) ----------------
__global__ void combine_w1_kernel(const float* __restrict__ W1) {
    int i = blockIdx.x * 256 + threadIdx.x;
    if (i >= 4 * H * H) return;
    int r = i / H, c = i % H;
    float v;
    if (r < 128)       v = W1[r * H + c];
    else if (r < 256)  v = W1[r * H + c] + W1[(r + 256) * H + c];  // hE + hE
    else if (r < 384)  v = W1[r * H + c];
    else               v = W1[(r + 128) * H + c];                  // hVa rows 512..639
    g_W1eff[i] = v;
}

// ---------------- kernel 1: node message MLP + sum_K + LN1 ----------------
__global__ void __launch_bounds__(128, 2)
node_msg_kernel(const float* __restrict__ hV, const float* __restrict__ hVa,
                const float* __restrict__ hE,
                const float* __restrict__ b1, const float* __restrict__ W2,
                const float* __restrict__ b2, const float* __restrict__ W3,
                const float* __restrict__ b3,
                const float* __restrict__ g1, const float* __restrict__ be1,
                const float* __restrict__ maskA, const int* __restrict__ Eidx,
                int Nn) {
    extern __shared__ float sm[];
    float* sW   = sm;                       // 16384
    float* sX   = sW + H * H;               // 48*132 = 6336
    float* sP   = sX + KNB * PITCH;         // 8*128
    float* sxV  = sP + 8 * H;               // 128
    float* sV0  = sxV + H;                  // 128
    float* sRed = sV0 + H;                  // 64
    int*   sIdx = (int*)(sRed + 64);        // 48 ints

    const int p = blockIdx.x;
    const int b = p / Nn;
    const int tid = threadIdx.x;
    const int tn = tid & 15, tm = tid >> 4;

    sxV[tid] = hV[(size_t)p * H + tid];
    if (tid < KNB) sIdx[tid] = Eidx[(size_t)p * KNB + tid];
    __syncthreads();

    // shared contribution of h_V_i through W1eff rows [0:128) (rank-1 hoist)
    {
        float a = 0.f;
        const float* Wv = g_W1eff;
#pragma unroll 4
        for (int k = 0; k < H; k++) a += sxV[k] * Wv[k * H + tid];
        sV0[tid] = a;
    }

    float acc[6][8];
#pragma unroll
    for (int j = 0; j < 6; j++)
#pragma unroll
        for (int i = 0; i < 8; i++) acc[j][i] = 0.f;

    const float* hVb  = hV  + (size_t)b * Nn * H;
    const float* hVab = hVa + (size_t)b * Nn * H;
    const float* hEp  = hE  + (size_t)p * KNB * H;

    // segment 0: h_E
    load_W(sW, g_W1eff + 1 * H * H, tid);
    load_rows(sX, hEp, tid);
    __syncthreads();
    gemm48(sX, sW, tm, tn, acc);
    __syncthreads();
    // segment 1: gather h_V[idx]
    load_W(sW, g_W1eff + 2 * H * H, tid);
    load_gather(sX, hVb, sIdx, tid);
    __syncthreads();
    gemm48(sX, sW, tm, tn, acc);
    __syncthreads();
    // segment 2: gather h_V_atom[idx]
    load_W(sW, g_W1eff + 3 * H * H, tid);
    load_gather(sX, hVab, sIdx, tid);
    __syncthreads();
    gemm48(sX, sW, tm, tn, acc);
    __syncthreads();

    // hidden1 = gelu(acc + v0 + b1) -> sX ; stage W2
#pragma unroll
    for (int i = 0; i < 8; i++) {
        int col = tn * 8 + i;
        float add = sV0[col] + b1[col];
#pragma unroll
        for (int j = 0; j < 6; j++) {
            sX[(tm * 6 + j) * PITCH + col] = gelu_exact(acc[j][i] + add);
            acc[j][i] = (j == 5) ? 0.f : acc[j][i];
        }
    }
#pragma unroll
    for (int j = 0; j < 6; j++)
#pragma unroll
        for (int i = 0; i < 8; i++) acc[j][i] = 0.f;
    load_W(sW, W2, tid);
    __syncthreads();
    gemm48(sX, sW, tm, tn, acc);
    __syncthreads();

    // hidden2 = gelu(acc + b2) -> sX ; stage W3
#pragma unroll
    for (int i = 0; i < 8; i++) {
        int col = tn * 8 + i;
        float add = b2[col];
#pragma unroll
        for (int j = 0; j < 6; j++) sX[(tm * 6 + j) * PITCH + col] = gelu_exact(acc[j][i] + add);
    }
#pragma unroll
    for (int j = 0; j < 6; j++)
#pragma unroll
        for (int i = 0; i < 8; i++) acc[j][i] = 0.f;
    load_W(sW, W3, tid);
    __syncthreads();
    gemm48(sX, sW, tm, tn, acc);

    // message = acc + b3 ; mask_attend ; per-column partial sums
    float msum[8];
#pragma unroll
    for (int i = 0; i < 8; i++) msum[i] = 0.f;
#pragma unroll
    for (int j = 0; j < 6; j++) {
        float mk = maskA[(size_t)p * KNB + tm * 6 + j];
#pragma unroll
        for (int i = 0; i < 8; i++) msum[i] += mk * (acc[j][i] + b3[tn * 8 + i]);
    }
#pragma unroll
    for (int i = 0; i < 8; i++) sP[tm * H + tn * 8 + i] = msum[i];
    __syncthreads();

    // reduce over the 8 tm-groups, residual + LN1
    float dh = 0.f;
#pragma unroll
    for (int r = 0; r < 8; r++) dh += sP[r * H + tid];
    float u = sxV[tid] + dh * (1.0f / 30.0f);

    float s = u;
#pragma unroll
    for (int off = 16; off > 0; off >>= 1) s += __shfl_xor_sync(0xffffffffu, s, off);
    if ((tid & 31) == 0) sRed[tid >> 5] = s;
    __syncthreads();
    float mean = (sRed[0] + sRed[1] + sRed[2] + sRed[3]) * (1.0f / H);
    float d = u - mean;
    float v2 = d * d;
#pragma unroll
    for (int off = 16; off > 0; off >>= 1) v2 += __shfl_xor_sync(0xffffffffu, v2, off);
    if ((tid & 31) == 0) sRed[4 + (tid >> 5)] = v2;
    __syncthreads();
    float var = (sRed[4] + sRed[5] + sRed[6] + sRed[7]) * (1.0f / H);
    g_hV1[(size_t)p * H + tid] = d * rsqrtf(var + 1e-5f) * g1[tid] + be1[tid];
}

// ---------------- kernel 2: FFN + LN2 + mask_V (8 nodes per block) ----------------
__global__ void __launch_bounds__(128)
ffn_kernel(const float* __restrict__ W_in, const float* __restrict__ b_in,
           const float* __restrict__ W_out, const float* __restrict__ b_out,
           const float* __restrict__ g2, const float* __restrict__ be2,
           const float* __restrict__ maskV, float* __restrict__ outV) {
    __shared__ float sx[8 * H];
    __shared__ float sh[8 * 512];
    __shared__ float sRed[8];
    const int tid = threadIdx.x;
    const int p0 = blockIdx.x * 8;

    for (int i = tid; i < 8 * H; i += 128) sx[i] = g_hV1[(size_t)p0 * H + i];
    __syncthreads();

    float a[4][8];
#pragma unroll
    for (int r = 0; r < 4; r++)
#pragma unroll
        for (int nn = 0; nn < 8; nn++) a[r][nn] = 0.f;

#pragma unroll 2
    for (int k = 0; k < H; k++) {
        float w[4];
#pragma unroll
        for (int r = 0; r < 4; r++) w[r] = W_in[k * 512 + tid + 128 * r];
#pragma unroll
        for (int nn = 0; nn < 8; nn++) {
            float xv = sx[nn * H + k];
#pragma unroll
            for (int r = 0; r < 4; r++) a[r][nn] += w[r] * xv;
        }
    }
#pragma unroll
    for (int r = 0; r < 4; r++) {
        float bb = b_in[tid + 128 * r];
#pragma unroll
        for (int nn = 0; nn < 8; nn++)
            sh[nn * 512 + tid + 128 * r] = gelu_exact(a[r][nn] + bb);
    }
    __syncthreads();

    float o[8];
#pragma unroll
    for (int nn = 0; nn < 8; nn++) o[nn] = 0.f;
#pragma unroll 2
    for (int k = 0; k < 512; k++) {
        float w = W_out[k * H + tid];
#pragma unroll
        for (int nn = 0; nn < 8; nn++) o[nn] += w * sh[nn * 512 + k];
    }

    float bo = b_out[tid];
    for (int nn = 0; nn < 8; nn++) {
        float u = sx[nn * H + tid] + o[nn] + bo;
        float s = u;
#pragma unroll
        for (int off = 16; off > 0; off >>= 1) s += __shfl_xor_sync(0xffffffffu, s, off);
        if ((tid & 31) == 0) sRed[tid >> 5] = s;
        __syncthreads();
        float mean = (sRed[0] + sRed[1] + sRed[2] + sRed[3]) * (1.0f / H);
        float d = u - mean;
        float v2 = d * d;
#pragma unroll
        for (int off = 16; off > 0; off >>= 1) v2 += __shfl_xor_sync(0xffffffffu, v2, off);
        if ((tid & 31) == 0) sRed[4 + (tid >> 5)] = v2;
        __syncthreads();
        float var = (sRed[4] + sRed[5] + sRed[6] + sRed[7]) * (1.0f / H);
        float res = (d * rsqrtf(var + 1e-5f) * g2[tid] + be2[tid]) * maskV[p0 + nn];
        outV[(size_t)(p0 + nn) * H + tid] = res;
        __syncthreads();
    }
}

// ---------------- kernel 3: edge-update MLP + LN3 ----------------
__global__ void __launch_bounds__(128, 2)
edge_kernel(const float* __restrict__ hVf, const float* __restrict__ hE,
            const float* __restrict__ W11, const float* __restrict__ b11,
            const float* __restrict__ W12, const float* __restrict__ b12,
            const float* __restrict__ W13, const float* __restrict__ b13,
            const float* __restrict__ g3, const float* __restrict__ be3,
            const int* __restrict__ Eidx, float* __restrict__ outE, int Nn) {
    extern __shared__ float sm[];
    float* sW   = sm;
    float* sX   = sW + H * H;
    float* sP   = sX + KNB * PITCH;     // unused here but keep layout
    float* sxV  = sP + 8 * H;
    float* sV0  = sxV + H;
    float* sRed = sV0 + H;
    int*   sIdx = (int*)(sRed + 64);

    const int p = blockIdx.x;
    const int b = p / Nn;
    const int tid = threadIdx.x;
    const int tn = tid & 15, tm = tid >> 4;

    sxV[tid] = hVf[(size_t)p * H + tid];
    if (tid < KNB) sIdx[tid] = Eidx[(size_t)p * KNB + tid];
    __syncthreads();

    {
        float a = 0.f;
#pragma unroll 4
        for (int k = 0; k < H; k++) a += sxV[k] * W11[k * H + tid];  // rows [0:128)
        sV0[tid] = a;
    }

    float acc[6][8];
#pragma unroll
    for (int j = 0; j < 6; j++)
#pragma unroll
        for (int i = 0; i < 8; i++) acc[j][i] = 0.f;

    const float* hVb = hVf + (size_t)b * Nn * H;
    const float* hEp = hE + (size_t)p * KNB * H;

    // segment 0: h_E  (W11 rows [128:256))
    load_W(sW, W11 + 1 * H * H, tid);
    load_rows(sX, hEp, tid);
    __syncthreads();
    gemm48(sX, sW, tm, tn, acc);
    __syncthreads();
    // segment 1: gather h_V_final[idx]  (W11 rows [256:384))
    load_W(sW, W11 + 2 * H * H, tid);
    load_gather(sX, hVb, sIdx, tid);
    __syncthreads();
    gemm48(sX, sW, tm, tn, acc);
    __syncthreads();

#pragma unroll
    for (int i = 0; i < 8; i++) {
        int col = tn * 8 + i;
        float add = sV0[col] + b11[col];
#pragma unroll
        for (int j = 0; j < 6; j++) sX[(tm * 6 + j) * PITCH + col] = gelu_exact(acc[j][i] + add);
    }
#pragma unroll
    for (int j = 0; j < 6; j++)
#pragma unroll
        for (int i = 0; i < 8; i++) acc[j][i] = 0.f;
    load_W(sW, W12, tid);
    __syncthreads();
    gemm48(sX, sW, tm, tn, acc);
    __syncthreads();

#pragma unroll
    for (int i = 0; i < 8; i++) {
        int col = tn * 8 + i;
        float add = b12[col];
#pragma unroll
        for (int j = 0; j < 6; j++) sX[(tm * 6 + j) * PITCH + col] = gelu_exact(acc[j][i] + add);
    }
#pragma unroll
    for (int j = 0; j < 6; j++)
#pragma unroll
        for (int i = 0; i < 8; i++) acc[j][i] = 0.f;
    load_W(sW, W13, tid);
    __syncthreads();
    gemm48(sX, sW, tm, tn, acc);
    __syncthreads();

    // message (+b13) -> sX rows
#pragma unroll
    for (int i = 0; i < 8; i++) {
        int col = tn * 8 + i;
        float bb = b13[col];
#pragma unroll
        for (int j = 0; j < 6; j++) sX[(tm * 6 + j) * PITCH + col] = acc[j][i] + bb;
    }
    __syncthreads();

    // per-edge LN3: warp per row
    const int warp = tid >> 5, lane = tid & 31;
    for (int r = warp; r < KNB; r += 4) {
        float v[4];
        float ssum = 0.f;
#pragma unroll
        for (int q = 0; q < 4; q++) {
            int col = lane + 32 * q;
            v[q] = sX[r * PITCH + col] + hEp[r * H + col];
            ssum += v[q];
        }
#pragma unroll
        for (int off = 16; off > 0; off >>= 1) ssum += __shfl_xor_sync(0xffffffffu, ssum, off);
        float mean = ssum * (1.0f / H);
        float vs = 0.f;
#pragma unroll
        for (int q = 0; q < 4; q++) { v[q] -= mean; vs += v[q] * v[q]; }
#pragma unroll
        for (int off = 16; off > 0; off >>= 1) vs += __shfl_xor_sync(0xffffffffu, vs, off);
        float rs = rsqrtf(vs * (1.0f / H) + 1e-5f);
#pragma unroll
        for (int q = 0; q < 4; q++) {
            int col = lane + 32 * q;
            outE[(size_t)p * KNB * H + r * H + col] = v[q] * rs * g3[col] + be3[col];
        }
    }
}

// ---------------- launch ----------------
extern "C" void kernel_launch(void* const* d_in, const int* in_sizes, int n_in,
                              void* d_out, int out_size) {
    const float* hV    = (const float*)d_in[0];
    const float* hVa   = (const float*)d_in[1];
    const float* hE    = (const float*)d_in[2];
    const float* W1    = (const float*)d_in[3];
    const float* b1    = (const float*)d_in[4];
    const float* W2    = (const float*)d_in[5];
    const float* b2    = (const float*)d_in[6];
    const float* W3    = (const float*)d_in[7];
    const float* b3    = (const float*)d_in[8];
    const float* W11   = (const float*)d_in[9];
    const float* b11   = (const float*)d_in[10];
    const float* W12   = (const float*)d_in[11];
    const float* b12   = (const float*)d_in[12];
    const float* W13   = (const float*)d_in[13];
    const float* b13   = (const float*)d_in[14];
    const float* W_in  = (const float*)d_in[15];
    const float* b_in  = (const float*)d_in[16];
    const float* W_out = (const float*)d_in[17];
    const float* b_out = (const float*)d_in[18];
    const float* g1    = (const float*)d_in[19];
    const float* be1   = (const float*)d_in[20];
    const float* g2    = (const float*)d_in[21];
    const float* be2   = (const float*)d_in[22];
    const float* g3    = (const float*)d_in[23];
    const float* be3   = (const float*)d_in[24];
    const float* maskV = (const float*)d_in[25];
    const float* maskA = (const float*)d_in[26];
    const int*   Eidx  = (const int*)d_in[27];

    const int BN = in_sizes[0] / H;   // B*N = 4096
    const int Nn = NN_CONST;          // N = 2048 (fixed problem shape)

    float* outV = (float*)d_out;
    float* outE = (float*)d_out + (size_t)BN * H;

    size_t smem1 = (size_t)(H * H + KNB * PITCH + 8 * H + H + H + 64) * sizeof(float)
                   + KNB * sizeof(int);

    cudaFuncSetAttribute(node_msg_kernel, cudaFuncAttributeMaxDynamicSharedMemorySize, (int)smem1);
    cudaFuncSetAttribute(edge_kernel,     cudaFuncAttributeMaxDynamicSharedMemorySize, (int)smem1);

    combine_w1_kernel<<<(4 * H * H + 255) / 256, 256>>>(W1);
    node_msg_kernel<<<BN, 128, smem1>>>(hV, hVa, hE, b1, W2, b2, W3, b3,
                                        g1, be1, maskA, Eidx, Nn);
    ffn_kernel<<<BN / 8, 128>>>(W_in, b_in, W_out, b_out, g2, be2, maskV, outV);
    edge_kernel<<<BN, 128, smem1>>>(outV, hE, W11, b11, W12, b12, W13, b13,
                                    g3, be3, Eidx, outE, Nn);
}

// round 3
// speedup vs baseline: 1.4445x; 1.4445x over previous
#include <cuda_runtime.h>
#include <math.h>

#define H      128
#define KNB    48
#define PITCH  132      // smem row pitch (floats), 528B = 16B-aligned
#define NN_CONST 2048
#define BNTOT  4096

// ---------------- scratch (no allocs allowed) ----------------
__device__ float g_We1[H * H];        // folded W1 edge block: rows[128:256)+rows[384:512)
__device__ float g_D1[BNTOT * H];     // hV_i @ W1v + b1   (dest term, MLP1)
__device__ float g_P1[BNTOT * H];     // hV_j @ W1g + hVa_j @ W1a  (source term, MLP1)
__device__ float g_D2[BNTOT * H];     // hVf_i @ W11v + b11 (dest term, MLP2)
__device__ float g_P2[BNTOT * H];     // hVf_j @ W11g       (source term, MLP2)
__device__ float g_hV1[BNTOT * H];    // h_V after LN1 (pre-FFN)

__device__ __forceinline__ float gelu_exact(float x) {
    return 0.5f * x * (1.0f + erff(x * 0.70710678118654752f));
}

// ---------------- smem loaders ----------------
__device__ __forceinline__ void load_W_half(float* sW, const float* __restrict__ g, int tid) {
    const float4* s = (const float4*)g;
    float4* d = (float4*)sW;
#pragma unroll
    for (int i = 0; i < 16; i++) d[tid + 128 * i] = s[tid + 128 * i];   // 64*128 floats
}

__device__ __forceinline__ void load_rows(float* sX, const float* __restrict__ src, int tid) {
    for (int i = tid; i < KNB * (H / 4); i += 128) {
        int e = i >> 5, q = i & 31;
        float4 v = ((const float4*)src)[e * (H / 4) + q];
        *(float4*)(sX + e * PITCH + q * 4) = v;
    }
}

// ---------------- 48x128 @ (64-slice of K) GEMM, register tile 6x8 ----------------
// 128 threads: tn = tid&15 (8 cols), tm = tid>>4 (6 rows)
__device__ __forceinline__ void gemm_part(const float* __restrict__ sX, int koff,
                                          const float* __restrict__ sW,
                                          int tm, int tn, float acc[6][8]) {
    const float* x  = sX + tm * 6 * PITCH + koff;
    const float* wb = sW + tn * 8;
#pragma unroll 2
    for (int k4 = 0; k4 < 64; k4 += 4) {
        float A[6][4];
#pragma unroll
        for (int j = 0; j < 6; j++) {
            float4 t = *(const float4*)(x + j * PITCH + k4);
            A[j][0] = t.x; A[j][1] = t.y; A[j][2] = t.z; A[j][3] = t.w;
        }
#pragma unroll
        for (int kk = 0; kk < 4; kk++) {
            const float* w = wb + (k4 + kk) * H;
            float4 b0 = *(const float4*)w;
            float4 b1 = *(const float4*)(w + 4);
            float B[8];
            B[0] = b0.x; B[1] = b0.y; B[2] = b0.z; B[3] = b0.w;
            B[4] = b1.x; B[5] = b1.y; B[6] = b1.z; B[7] = b1.w;
#pragma unroll
            for (int j = 0; j < 6; j++) {
                float av = A[j][kk];
#pragma unroll
                for (int i = 0; i < 8; i++)
                    acc[j][i] = fmaf(av, B[i], acc[j][i]);
            }
        }
    }
}

__device__ __forceinline__ void zero_acc(float acc[6][8]) {
#pragma unroll
    for (int j = 0; j < 6; j++)
#pragma unroll
        for (int i = 0; i < 8; i++) acc[j][i] = 0.f;
}

// full K=128 GEMM with W staged in two 32KB halves
__device__ __forceinline__ void gemm_staged(float* sW, const float* __restrict__ Wg,
                                            const float* __restrict__ sX,
                                            int tm, int tn, int tid, float acc[6][8]) {
    load_W_half(sW, Wg, tid);
    __syncthreads();
    gemm_part(sX, 0, sW, tm, tn, acc);
    __syncthreads();
    load_W_half(sW, Wg + 64 * H, tid);
    __syncthreads();
    gemm_part(sX, 64, sW, tm, tn, acc);
}

// ---------------- kernel 0: fold W1 edge block ----------------
__global__ void fold_we1_kernel(const float* __restrict__ W1) {
    int i = blockIdx.x * 256 + threadIdx.x;
    if (i < H * H)
        g_We1[i] = W1[(128 * H) + i] + W1[(384 * H) + i];
}

// ---------------- precompute 1: per-node terms for MLP1 ----------------
__global__ void __launch_bounds__(128)
pre1_kernel(const float* __restrict__ hV, const float* __restrict__ hVa,
            const float* __restrict__ W1, const float* __restrict__ b1) {
    __shared__ float sx[8 * H], sxa[8 * H];
    const int tid = threadIdx.x;
    const int p0 = blockIdx.x * 8;
    for (int i = tid; i < 8 * H; i += 128) {
        sx[i]  = hV[(size_t)p0 * H + i];
        sxa[i] = hVa[(size_t)p0 * H + i];
    }
    __syncthreads();
    float dacc[8], pacc[8];
#pragma unroll
    for (int n = 0; n < 8; n++) { dacc[n] = 0.f; pacc[n] = 0.f; }
#pragma unroll 2
    for (int k = 0; k < H; k++) {
        float wv = W1[k * H + tid];
        float wg = W1[(256 + k) * H + tid];
        float wa = W1[(512 + k) * H + tid];
#pragma unroll
        for (int n = 0; n < 8; n++) {
            dacc[n] = fmaf(sx[n * H + k], wv, dacc[n]);
            pacc[n] = fmaf(sx[n * H + k], wg, pacc[n]);
            pacc[n] = fmaf(sxa[n * H + k], wa, pacc[n]);
        }
    }
    float bb = b1[tid];
#pragma unroll
    for (int n = 0; n < 8; n++) {
        g_D1[(size_t)(p0 + n) * H + tid] = dacc[n] + bb;
        g_P1[(size_t)(p0 + n) * H + tid] = pacc[n];
    }
}

// ---------------- precompute 2: per-node terms for MLP2 ----------------
__global__ void __launch_bounds__(128)
pre2_kernel(const float* __restrict__ hVf, const float* __restrict__ W11,
            const float* __restrict__ b11) {
    __shared__ float sx[8 * H];
    const int tid = threadIdx.x;
    const int p0 = blockIdx.x * 8;
    for (int i = tid; i < 8 * H; i += 128) sx[i] = hVf[(size_t)p0 * H + i];
    __syncthreads();
    float dacc[8], pacc[8];
#pragma unroll
    for (int n = 0; n < 8; n++) { dacc[n] = 0.f; pacc[n] = 0.f; }
#pragma unroll 2
    for (int k = 0; k < H; k++) {
        float wv = W11[k * H + tid];
        float wg = W11[(256 + k) * H + tid];
#pragma unroll
        for (int n = 0; n < 8; n++) {
            dacc[n] = fmaf(sx[n * H + k], wv, dacc[n]);
            pacc[n] = fmaf(sx[n * H + k], wg, pacc[n]);
        }
    }
    float bb = b11[tid];
#pragma unroll
    for (int n = 0; n < 8; n++) {
        g_D2[(size_t)(p0 + n) * H + tid] = dacc[n] + bb;
        g_P2[(size_t)(p0 + n) * H + tid] = pacc[n];
    }
}

// ---------------- kernel 1: node message (3 staged GEMMs) + sum_K + LN1 ----------------
__global__ void __launch_bounds__(128, 3)
node_msg_kernel(const float* __restrict__ hV, const float* __restrict__ hE,
                const float* __restrict__ W2, const float* __restrict__ b2,
                const float* __restrict__ W3, const float* __restrict__ b3,
                const float* __restrict__ g1, const float* __restrict__ be1,
                const float* __restrict__ maskA, const int* __restrict__ Eidx,
                int Nn) {
    extern __shared__ float sm[];
    float* sW   = sm;                    // 64*128 = 8192 floats (32KB half)
    float* sX   = sW + 64 * H;           // 48*132
    float* sP   = sX + KNB * PITCH;      // 8*128
    float* sxV  = sP + 8 * H;            // 128
    float* sD   = sxV + H;               // 128
    float* sRed = sD + H;                // 64
    int*   sIdx = (int*)(sRed + 64);     // 48

    const int p = blockIdx.x;
    const int b = p / Nn;
    const int tid = threadIdx.x;
    const int tn = tid & 15, tm = tid >> 4;

    sxV[tid] = hV[(size_t)p * H + tid];
    sD[tid]  = g_D1[(size_t)p * H + tid];
    if (tid < KNB) sIdx[tid] = Eidx[(size_t)p * KNB + tid];

    float acc[6][8];
    zero_acc(acc);

    const float* hEp = hE + (size_t)p * KNB * H;
    load_rows(sX, hEp, tid);
    __syncthreads();

    // GEMM1: T = hE @ We1(folded)
    gemm_staged(sW, g_We1, sX, tm, tn, tid, acc);

    // epilogue1: H1 = gelu(T + D1[i] + P1[src]); writes own sX rows (warp-local, no sync needed)
    {
        const float* P1b = g_P1 + (size_t)b * Nn * H;
#pragma unroll
        for (int j = 0; j < 6; j++) {
            int row = tm * 6 + j;
            const float* pr = P1b + (size_t)sIdx[row] * H + tn * 8;
            float4 p0 = *(const float4*)pr;
            float4 p1 = *(const float4*)(pr + 4);
            float pv[8];
            pv[0]=p0.x; pv[1]=p0.y; pv[2]=p0.z; pv[3]=p0.w;
            pv[4]=p1.x; pv[5]=p1.y; pv[6]=p1.z; pv[7]=p1.w;
#pragma unroll
            for (int i = 0; i < 8; i++) {
                int col = tn * 8 + i;
                sX[row * PITCH + col] = gelu_exact(acc[j][i] + sD[col] + pv[i]);
            }
        }
    }
    zero_acc(acc);
    __syncthreads();

    // GEMM2
    gemm_staged(sW, W2, sX, tm, tn, tid, acc);
#pragma unroll
    for (int j = 0; j < 6; j++) {
        int row = tm * 6 + j;
#pragma unroll
        for (int i = 0; i < 8; i++) {
            int col = tn * 8 + i;
            sX[row * PITCH + col] = gelu_exact(acc[j][i] + b2[col]);
        }
    }
    zero_acc(acc);
    __syncthreads();

    // GEMM3
    gemm_staged(sW, W3, sX, tm, tn, tid, acc);

    // masked sum over K, per-column partials
    float msum[8];
#pragma unroll
    for (int i = 0; i < 8; i++) msum[i] = 0.f;
#pragma unroll
    for (int j = 0; j < 6; j++) {
        float mk = maskA[(size_t)p * KNB + tm * 6 + j];
#pragma unroll
        for (int i = 0; i < 8; i++) msum[i] += mk * (acc[j][i] + b3[tn * 8 + i]);
    }
#pragma unroll
    for (int i = 0; i < 8; i++) sP[tm * H + tn * 8 + i] = msum[i];
    __syncthreads();

    float dh = 0.f;
#pragma unroll
    for (int r = 0; r < 8; r++) dh += sP[r * H + tid];
    float u = sxV[tid] + dh * (1.0f / 30.0f);

    float s = u;
#pragma unroll
    for (int off = 16; off > 0; off >>= 1) s += __shfl_xor_sync(0xffffffffu, s, off);
    if ((tid & 31) == 0) sRed[tid >> 5] = s;
    __syncthreads();
    float mean = (sRed[0] + sRed[1] + sRed[2] + sRed[3]) * (1.0f / H);
    float d = u - mean;
    float v2 = d * d;
#pragma unroll
    for (int off = 16; off > 0; off >>= 1) v2 += __shfl_xor_sync(0xffffffffu, v2, off);
    if ((tid & 31) == 0) sRed[4 + (tid >> 5)] = v2;
    __syncthreads();
    float var = (sRed[4] + sRed[5] + sRed[6] + sRed[7]) * (1.0f / H);
    g_hV1[(size_t)p * H + tid] = d * rsqrtf(var + 1e-5f) * g1[tid] + be1[tid];
}

// ---------------- kernel 2: FFN + LN2 + mask_V (8 nodes per block) ----------------
__global__ void __launch_bounds__(128)
ffn_kernel(const float* __restrict__ W_in, const float* __restrict__ b_in,
           const float* __restrict__ W_out, const float* __restrict__ b_out,
           const float* __restrict__ g2, const float* __restrict__ be2,
           const float* __restrict__ maskV, float* __restrict__ outV) {
    __shared__ float sx[8 * H];
    __shared__ float sh[8 * 512];
    __shared__ float sRed[8];
    const int tid = threadIdx.x;
    const int p0 = blockIdx.x * 8;

    for (int i = tid; i < 8 * H; i += 128) sx[i] = g_hV1[(size_t)p0 * H + i];
    __syncthreads();

    float a[4][8];
#pragma unroll
    for (int r = 0; r < 4; r++)
#pragma unroll
        for (int nn = 0; nn < 8; nn++) a[r][nn] = 0.f;

#pragma unroll 2
    for (int k = 0; k < H; k++) {
        float w[4];
#pragma unroll
        for (int r = 0; r < 4; r++) w[r] = W_in[k * 512 + tid + 128 * r];
#pragma unroll
        for (int nn = 0; nn < 8; nn++) {
            float xv = sx[nn * H + k];
#pragma unroll
            for (int r = 0; r < 4; r++) a[r][nn] = fmaf(w[r], xv, a[r][nn]);
        }
    }
#pragma unroll
    for (int r = 0; r < 4; r++) {
        float bb = b_in[tid + 128 * r];
#pragma unroll
        for (int nn = 0; nn < 8; nn++)
            sh[nn * 512 + tid + 128 * r] = gelu_exact(a[r][nn] + bb);
    }
    __syncthreads();

    float o[8];
#pragma unroll
    for (int nn = 0; nn < 8; nn++) o[nn] = 0.f;
#pragma unroll 2
    for (int k = 0; k < 512; k++) {
        float w = W_out[k * H + tid];
#pragma unroll
        for (int nn = 0; nn < 8; nn++) o[nn] = fmaf(w, sh[nn * 512 + k], o[nn]);
    }

    float bo = b_out[tid];
    for (int nn = 0; nn < 8; nn++) {
        float u = sx[nn * H + tid] + o[nn] + bo;
        float s = u;
#pragma unroll
        for (int off = 16; off > 0; off >>= 1) s += __shfl_xor_sync(0xffffffffu, s, off);
        if ((tid & 31) == 0) sRed[tid >> 5] = s;
        __syncthreads();
        float mean = (sRed[0] + sRed[1] + sRed[2] + sRed[3]) * (1.0f / H);
        float d = u - mean;
        float v2 = d * d;
#pragma unroll
        for (int off = 16; off > 0; off >>= 1) v2 += __shfl_xor_sync(0xffffffffu, v2, off);
        if ((tid & 31) == 0) sRed[4 + (tid >> 5)] = v2;
        __syncthreads();
        float var = (sRed[4] + sRed[5] + sRed[6] + sRed[7]) * (1.0f / H);
        float res = (d * rsqrtf(var + 1e-5f) * g2[tid] + be2[tid]) * maskV[p0 + nn];
        outV[(size_t)(p0 + nn) * H + tid] = res;
        __syncthreads();
    }
}

// ---------------- kernel 3: edge update (3 staged GEMMs) + LN3 ----------------
__global__ void __launch_bounds__(128, 3)
edge_kernel(const float* __restrict__ hE,
            const float* __restrict__ W11, const float* __restrict__ W12,
            const float* __restrict__ b12, const float* __restrict__ W13,
            const float* __restrict__ b13,
            const float* __restrict__ g3, const float* __restrict__ be3,
            const int* __restrict__ Eidx, float* __restrict__ outE, int Nn) {
    extern __shared__ float sm[];
    float* sW   = sm;                    // 8192
    float* sX   = sW + 64 * H;           // 48*132
    float* sD   = sX + KNB * PITCH;      // 128
    int*   sIdx = (int*)(sD + H);        // 48

    const int p = blockIdx.x;
    const int b = p / Nn;
    const int tid = threadIdx.x;
    const int tn = tid & 15, tm = tid >> 4;

    sD[tid] = g_D2[(size_t)p * H + tid];
    if (tid < KNB) sIdx[tid] = Eidx[(size_t)p * KNB + tid];

    float acc[6][8];
    zero_acc(acc);

    const float* hEp = hE + (size_t)p * KNB * H;
    load_rows(sX, hEp, tid);
    __syncthreads();

    // GEMM1: T = hE @ W11[128:384)... (edge block = rows 128:256)
    gemm_staged(sW, W11 + H * H, sX, tm, tn, tid, acc);

    // epilogue1: H1 = gelu(T + D2[i] + P2[src])
    {
        const float* P2b = g_P2 + (size_t)b * Nn * H;
#pragma unroll
        for (int j = 0; j < 6; j++) {
            int row = tm * 6 + j;
            const float* pr = P2b + (size_t)sIdx[row] * H + tn * 8;
            float4 p0 = *(const float4*)pr;
            float4 p1 = *(const float4*)(pr + 4);
            float pv[8];
            pv[0]=p0.x; pv[1]=p0.y; pv[2]=p0.z; pv[3]=p0.w;
            pv[4]=p1.x; pv[5]=p1.y; pv[6]=p1.z; pv[7]=p1.w;
#pragma unroll
            for (int i = 0; i < 8; i++) {
                int col = tn * 8 + i;
                sX[row * PITCH + col] = gelu_exact(acc[j][i] + sD[col] + pv[i]);
            }
        }
    }
    zero_acc(acc);
    __syncthreads();

    // GEMM2
    gemm_staged(sW, W12, sX, tm, tn, tid, acc);
#pragma unroll
    for (int j = 0; j < 6; j++) {
        int row = tm * 6 + j;
#pragma unroll
        for (int i = 0; i < 8; i++) {
            int col = tn * 8 + i;
            sX[row * PITCH + col] = gelu_exact(acc[j][i] + b12[col]);
        }
    }
    zero_acc(acc);
    __syncthreads();

    // GEMM3
    gemm_staged(sW, W13, sX, tm, tn, tid, acc);

    // message (+b13) -> own sX rows
#pragma unroll
    for (int j = 0; j < 6; j++) {
        int row = tm * 6 + j;
#pragma unroll
        for (int i = 0; i < 8; i++) {
            int col = tn * 8 + i;
            sX[row * PITCH + col] = acc[j][i] + b13[col];
        }
    }
    __syncthreads();

    // per-edge LN3 (warp per row), residual with hE from global
    const int warp = tid >> 5, lane = tid & 31;
    for (int r = warp; r < KNB; r += 4) {
        float v[4];
        float ssum = 0.f;
#pragma unroll
        for (int q = 0; q < 4; q++) {
            int col = lane + 32 * q;
            v[q] = sX[r * PITCH + col] + hEp[r * H + col];
            ssum += v[q];
        }
#pragma unroll
        for (int off = 16; off > 0; off >>= 1) ssum += __shfl_xor_sync(0xffffffffu, ssum, off);
        float mean = ssum * (1.0f / H);
        float vs = 0.f;
#pragma unroll
        for (int q = 0; q < 4; q++) { v[q] -= mean; vs += v[q] * v[q]; }
#pragma unroll
        for (int off = 16; off > 0; off >>= 1) vs += __shfl_xor_sync(0xffffffffu, vs, off);
        float rs = rsqrtf(vs * (1.0f / H) + 1e-5f);
#pragma unroll
        for (int q = 0; q < 4; q++) {
            int col = lane + 32 * q;
            outE[(size_t)p * KNB * H + r * H + col] = v[q] * rs * g3[col] + be3[col];
        }
    }
}

// ---------------- launch ----------------
extern "C" void kernel_launch(void* const* d_in, const int* in_sizes, int n_in,
                              void* d_out, int out_size) {
    const float* hV    = (const float*)d_in[0];
    const float* hVa   = (const float*)d_in[1];
    const float* hE    = (const float*)d_in[2];
    const float* W1    = (const float*)d_in[3];
    const float* b1    = (const float*)d_in[4];
    const float* W2    = (const float*)d_in[5];
    const float* b2    = (const float*)d_in[6];
    const float* W3    = (const float*)d_in[7];
    const float* b3    = (const float*)d_in[8];
    const float* W11   = (const float*)d_in[9];
    const float* b11   = (const float*)d_in[10];
    const float* W12   = (const float*)d_in[11];
    const float* b12   = (const float*)d_in[12];
    const float* W13   = (const float*)d_in[13];
    const float* b13   = (const float*)d_in[14];
    const float* W_in  = (const float*)d_in[15];
    const float* b_in  = (const float*)d_in[16];
    const float* W_out = (const float*)d_in[17];
    const float* b_out = (const float*)d_in[18];
    const float* g1    = (const float*)d_in[19];
    const float* be1   = (const float*)d_in[20];
    const float* g2    = (const float*)d_in[21];
    const float* be2   = (const float*)d_in[22];
    const float* g3    = (const float*)d_in[23];
    const float* be3   = (const float*)d_in[24];
    const float* maskV = (const float*)d_in[25];
    const float* maskA = (const float*)d_in[26];
    const int*   Eidx  = (const int*)d_in[27];

    const int BN = in_sizes[0] / H;   // 4096
    const int Nn = NN_CONST;          // 2048

    float* outV = (float*)d_out;
    float* outE = (float*)d_out + (size_t)BN * H;

    size_t smemN = (size_t)(64 * H + KNB * PITCH + 8 * H + H + H + 64) * sizeof(float)
                   + KNB * sizeof(int);
    size_t smemE = (size_t)(64 * H + KNB * PITCH + H) * sizeof(float)
                   + KNB * sizeof(int);

    cudaFuncSetAttribute(node_msg_kernel, cudaFuncAttributeMaxDynamicSharedMemorySize, (int)smemN);
    cudaFuncSetAttribute(edge_kernel,     cudaFuncAttributeMaxDynamicSharedMemorySize, (int)smemE);

    fold_we1_kernel<<<(H * H + 255) / 256, 256>>>(W1);
    pre1_kernel<<<BN / 8, 128>>>(hV, hVa, W1, b1);
    node_msg_kernel<<<BN, 128, smemN>>>(hV, hE, W2, b2, W3, b3,
                                        g1, be1, maskA, Eidx, Nn);
    ffn_kernel<<<BN / 8, 128>>>(W_in, b_in, W_out, b_out, g2, be2, maskV, outV);
    pre2_kernel<<<BN / 8, 128>>>(outV, W11, b11);
    edge_kernel<<<BN, 128, smemE>>>(hE, W11, W12, b12, W13, b13,
                                    g3, be3, Eidx, outE, Nn);
}

// round 5
// speedup vs baseline: 2.5730x; 1.7813x over previous
#include <cuda_runtime.h>
#include <cstdint>
#include <math.h>

#define H      128
#define KNB    48
#define NN     2048
#define BNTOT  4096
#define XP     132          // sX pitch (floats)
#define WP     68           // sW pitch (floats)

// smem float layout (node kernel; edge kernel uses a prefix of it):
//  sX   [0      .. 16896)   128 x 132
//  sW   [16896  .. 25600)   128 x 68 (k-half of weight tile)
//  sD   [25600  .. 26624)   8 x 128
//  sAcc [26624  .. 27648)   8 x 128 (node only)
//  sIdx [27648  .. 28032)   384 ints
//  sRed [28032  .. 28048)
#define SMEMN_FLOATS 28048
#define SMEME_FLOATS 28048

// ---------------- device scratch ----------------
__device__ float g_Wt[6 * H * H];   // tf32-rounded, [n][k]: 0:We1 1:W2 2:W3 3:W11e 4:W12 5:W13
__device__ float g_D1[BNTOT * H];
__device__ float g_P1[BNTOT * H];
__device__ float g_D2[BNTOT * H];
__device__ float g_P2[BNTOT * H];
__device__ float g_hV1[BNTOT * H];

__device__ __forceinline__ float to_tf32(float x) {
    uint32_t u;
    asm("cvt.rna.tf32.f32 %0, %1;" : "=r"(u) : "f"(x));
    return __uint_as_float(u);
}

__device__ __forceinline__ float gelu_exact(float x) {
    return 0.5f * x * (1.0f + erff(x * 0.70710678118654752f));
}

__device__ __forceinline__ void mma_tf32(float d[4], const uint32_t a[4], const uint32_t b[2]) {
    asm volatile("mma.sync.aligned.m16n8k8.row.col.f32.tf32.tf32.f32 "
                 "{%0,%1,%2,%3}, {%4,%5,%6,%7}, {%8,%9}, {%0,%1,%2,%3};"
                 : "+f"(d[0]), "+f"(d[1]), "+f"(d[2]), "+f"(d[3])
                 : "r"(a[0]), "r"(a[1]), "r"(a[2]), "r"(a[3]), "r"(b[0]), "r"(b[1]));
}

// ---------------- 128x128x128 tf32 GEMM: sX[m][k] @ Wg[n][k]^T -> acc ----------------
// 4 warps, warp w owns rows [w*32, w*32+32). Weights streamed in two 64-k halves.
__device__ __forceinline__ void gemm_mma(const float* __restrict__ sX, float* __restrict__ sW,
                                         const float* __restrict__ Wg, int tid,
                                         float acc[2][16][4]) {
    const int w = tid >> 5, lane = tid & 31;
    const int lr = lane >> 2, lc = lane & 3;
    const float* sXw = sX + (w * 32 + lr) * XP + lc;
    const float* sWb = sW + lr * WP + lc;

#pragma unroll
    for (int h = 0; h < 2; h++) {
        __syncthreads();                       // sX ready / sW free
        // stage 128n x 64k weight half
#pragma unroll
        for (int i = 0; i < 16; i++) {
            int idx = tid + 128 * i;           // 2048 float4
            int n = idx >> 4, q = idx & 15;
            float4 v = *(const float4*)(Wg + n * H + h * 64 + q * 4);
            *(float4*)(sW + n * WP + q * 4) = v;
        }
        __syncthreads();
#pragma unroll
        for (int k8 = 0; k8 < 8; k8++) {
            const int kg = h * 64 + k8 * 8;
            uint32_t a[2][4];
#pragma unroll
            for (int mt = 0; mt < 2; mt++) {
                const float* ap = sXw + mt * (16 * XP) + kg;
                a[mt][0] = __float_as_uint(ap[0]);
                a[mt][1] = __float_as_uint(ap[8 * XP]);
                a[mt][2] = __float_as_uint(ap[4]);
                a[mt][3] = __float_as_uint(ap[8 * XP + 4]);
            }
            const float* bp = sWb + k8 * 8;
#pragma unroll
            for (int nt = 0; nt < 16; nt++) {
                uint32_t b[2];
                b[0] = __float_as_uint(bp[nt * (8 * WP)]);
                b[1] = __float_as_uint(bp[nt * (8 * WP) + 4]);
                mma_tf32(acc[0][nt], a[0], b);
                mma_tf32(acc[1][nt], a[1], b);
            }
        }
    }
}

__device__ __forceinline__ void zero_acc(float acc[2][16][4]) {
#pragma unroll
    for (int mt = 0; mt < 2; mt++)
#pragma unroll
        for (int nt = 0; nt < 16; nt++)
#pragma unroll
            for (int q = 0; q < 4; q++) acc[mt][nt][q] = 0.f;
}

__device__ __forceinline__ void store_acc(float* __restrict__ sX, int tid,
                                          const float acc[2][16][4]) {
    const int w = tid >> 5, lane = tid & 31;
    const int lr = lane >> 2, lc = lane & 3;
    float* cx = sX + (w * 32 + lr) * XP + 2 * lc;
#pragma unroll
    for (int mt = 0; mt < 2; mt++)
#pragma unroll
        for (int nt = 0; nt < 16; nt++) {
            *(float2*)(cx + mt * (16 * XP) + nt * 8) =
                make_float2(acc[mt][nt][0], acc[mt][nt][1]);
            *(float2*)(cx + mt * (16 * XP) + 8 * XP + nt * 8) =
                make_float2(acc[mt][nt][2], acc[mt][nt][3]);
        }
}

// ---------------- prep: transpose(+fold) weights into [n][k], tf32-rounded ----------------
__global__ void prep_weights(const float* __restrict__ W1, const float* __restrict__ W2,
                             const float* __restrict__ W3, const float* __restrict__ W11,
                             const float* __restrict__ W12, const float* __restrict__ W13) {
    int idx = blockIdx.x * 256 + threadIdx.x;
    if (idx >= 6 * H * H) return;
    int m = idx >> 14;
    int r = (idx >> 7) & 127;   // n
    int c = idx & 127;          // k
    float v;
    switch (m) {
        case 0: v = W1[(128 + c) * H + r] + W1[(384 + c) * H + r]; break;
        case 1: v = W2[c * H + r]; break;
        case 2: v = W3[c * H + r]; break;
        case 3: v = W11[(128 + c) * H + r]; break;
        case 4: v = W12[c * H + r]; break;
        default: v = W13[c * H + r]; break;
    }
    g_Wt[idx] = to_tf32(v);
}

// ---------------- pre1 / pre2 (per-node hoisted fp32 terms) ----------------
__global__ void __launch_bounds__(128)
pre1_kernel(const float* __restrict__ hV, const float* __restrict__ hVa,
            const float* __restrict__ W1, const float* __restrict__ b1) {
    __shared__ float sx[8 * H], sxa[8 * H];
    const int tid = threadIdx.x;
    const int p0 = blockIdx.x * 8;
    for (int i = tid; i < 8 * H; i += 128) {
        sx[i]  = hV[(size_t)p0 * H + i];
        sxa[i] = hVa[(size_t)p0 * H + i];
    }
    __syncthreads();
    float dacc[8], pacc[8];
#pragma unroll
    for (int n = 0; n < 8; n++) { dacc[n] = 0.f; pacc[n] = 0.f; }
#pragma unroll 2
    for (int k = 0; k < H; k++) {
        float wv = W1[k * H + tid];
        float wg = W1[(256 + k) * H + tid];
        float wa = W1[(512 + k) * H + tid];
#pragma unroll
        for (int n = 0; n < 8; n++) {
            dacc[n] = fmaf(sx[n * H + k], wv, dacc[n]);
            pacc[n] = fmaf(sx[n * H + k], wg, pacc[n]);
            pacc[n] = fmaf(sxa[n * H + k], wa, pacc[n]);
        }
    }
    float bb = b1[tid];
#pragma unroll
    for (int n = 0; n < 8; n++) {
        g_D1[(size_t)(p0 + n) * H + tid] = dacc[n] + bb;
        g_P1[(size_t)(p0 + n) * H + tid] = pacc[n];
    }
}

__global__ void __launch_bounds__(128)
pre2_kernel(const float* __restrict__ hVf, const float* __restrict__ W11,
            const float* __restrict__ b11) {
    __shared__ float sx[8 * H];
    const int tid = threadIdx.x;
    const int p0 = blockIdx.x * 8;
    for (int i = tid; i < 8 * H; i += 128) sx[i] = hVf[(size_t)p0 * H + i];
    __syncthreads();
    float dacc[8], pacc[8];
#pragma unroll
    for (int n = 0; n < 8; n++) { dacc[n] = 0.f; pacc[n] = 0.f; }
#pragma unroll 2
    for (int k = 0; k < H; k++) {
        float wv = W11[k * H + tid];
        float wg = W11[(256 + k) * H + tid];
#pragma unroll
        for (int n = 0; n < 8; n++) {
            dacc[n] = fmaf(sx[n * H + k], wv, dacc[n]);
            pacc[n] = fmaf(sx[n * H + k], wg, pacc[n]);
        }
    }
    float bb = b11[tid];
#pragma unroll
    for (int n = 0; n < 8; n++) {
        g_D2[(size_t)(p0 + n) * H + tid] = dacc[n] + bb;
        g_P2[(size_t)(p0 + n) * H + tid] = pacc[n];
    }
}

// ---------------- kernel 1: node message MLP (mma.sync tf32) + sum_K + LN1 ----------------
__global__ void __launch_bounds__(128, 2)
node_mma_kernel(const float* __restrict__ hV, const float* __restrict__ hE,
                const float* __restrict__ b2, const float* __restrict__ b3,
                const float* __restrict__ g1, const float* __restrict__ be1,
                const float* __restrict__ maskA, const int* __restrict__ Eidx) {
    extern __shared__ float smf[];
    float* sX   = smf;
    float* sW   = smf + 16896;
    float* sD   = smf + 25600;
    float* sAcc = smf + 26624;
    int*   sIdx = (int*)(smf + 27648);
    float* sRed = smf + 28032;

    const int tid = threadIdx.x;
    const int p0 = blockIdx.x * 8;
    const int bb = p0 >> 11;

    for (int i = tid; i < 8 * H; i += 128) {
        sD[i] = g_D1[(size_t)p0 * H + i];
        sAcc[i] = 0.f;
    }
    for (int i = tid; i < 8 * KNB; i += 128) sIdx[i] = Eidx[(size_t)p0 * KNB + i];

    float acc[2][16][4];

    for (int t = 0; t < 3; t++) {
        const int e0 = p0 * KNB + t * 128;
        const float* arow = hE + (size_t)(e0 + tid) * H;
        float* xr = sX + tid * XP;

        __syncthreads();
        // load A tile (hE rows), tf32-rounded
#pragma unroll 8
        for (int c = 0; c < 128; c += 4) {
            float4 v = *(const float4*)(arow + c);
            xr[c + 0] = to_tf32(v.x); xr[c + 1] = to_tf32(v.y);
            xr[c + 2] = to_tf32(v.z); xr[c + 3] = to_tf32(v.w);
        }

        // ---- GEMM1 ----
        zero_acc(acc);
        gemm_mma(sX, sW, g_Wt + 0 * H * H, tid, acc);
        __syncthreads();
        store_acc(sX, tid, acc);
        __syncthreads();
        // epi1: gelu(x + D1[node] + P1[src]) -> tf32
        {
            const int src = sIdx[t * 128 + tid];
            const int nl = (t * 128 + tid) / KNB;
            const float* pr = g_P1 + ((size_t)bb * NN + src) * H;
            const float* dn = sD + nl * H;
#pragma unroll 8
            for (int c = 0; c < 128; c += 4) {
                float4 x = *(float4*)(xr + c);
                float4 p = *(const float4*)(pr + c);
                xr[c + 0] = to_tf32(gelu_exact(x.x + dn[c + 0] + p.x));
                xr[c + 1] = to_tf32(gelu_exact(x.y + dn[c + 1] + p.y));
                xr[c + 2] = to_tf32(gelu_exact(x.z + dn[c + 2] + p.z));
                xr[c + 3] = to_tf32(gelu_exact(x.w + dn[c + 3] + p.w));
            }
        }

        // ---- GEMM2 ----
        zero_acc(acc);
        gemm_mma(sX, sW, g_Wt + 1 * H * H, tid, acc);
        __syncthreads();
        store_acc(sX, tid, acc);
        __syncthreads();
        // epi2: gelu(x + b2)
#pragma unroll 8
        for (int c = 0; c < 128; c += 4) {
            float4 x = *(float4*)(xr + c);
            float4 bv = *(const float4*)(b2 + c);
            xr[c + 0] = to_tf32(gelu_exact(x.x + bv.x));
            xr[c + 1] = to_tf32(gelu_exact(x.y + bv.y));
            xr[c + 2] = to_tf32(gelu_exact(x.z + bv.z));
            xr[c + 3] = to_tf32(gelu_exact(x.w + bv.w));
        }

        // ---- GEMM3 ----
        zero_acc(acc);
        gemm_mma(sX, sW, g_Wt + 2 * H * H, tid, acc);
        __syncthreads();
        store_acc(sX, tid, acc);
        __syncthreads();
        // epi3: msg = mask * (x + b3)
        {
            float mk = maskA[e0 + tid];
#pragma unroll 8
            for (int c = 0; c < 128; c += 4) {
                float4 x = *(float4*)(xr + c);
                float4 bv = *(const float4*)(b3 + c);
                xr[c + 0] = mk * (x.x + bv.x);
                xr[c + 1] = mk * (x.y + bv.y);
                xr[c + 2] = mk * (x.z + bv.z);
                xr[c + 3] = mk * (x.w + bv.w);
            }
        }
        __syncthreads();

        // segment-sum tile rows into per-node accumulators (col = tid)
        {
            int nl2 = (t * 128) / KNB;
            int nxt = (nl2 + 1) * KNB - t * 128;
            float a = sAcc[nl2 * H + tid];
            for (int r = 0; r < 128; r++) {
                if (r == nxt) { sAcc[nl2 * H + tid] = a; nl2++; nxt += KNB; a = sAcc[nl2 * H + tid]; }
                a += sX[r * XP + tid];
            }
            sAcc[nl2 * H + tid] = a;
        }
    }
    __syncthreads();

    // LN1 per node
    for (int n = 0; n < 8; n++) {
        float u = hV[(size_t)(p0 + n) * H + tid] + sAcc[n * H + tid] * (1.0f / 30.0f);
        float s = u;
#pragma unroll
        for (int off = 16; off > 0; off >>= 1) s += __shfl_xor_sync(0xffffffffu, s, off);
        if ((tid & 31) == 0) sRed[tid >> 5] = s;
        __syncthreads();
        float mean = (sRed[0] + sRed[1] + sRed[2] + sRed[3]) * (1.0f / H);
        float d = u - mean;
        float v2 = d * d;
#pragma unroll
        for (int off = 16; off > 0; off >>= 1) v2 += __shfl_xor_sync(0xffffffffu, v2, off);
        if ((tid & 31) == 0) sRed[4 + (tid >> 5)] = v2;
        __syncthreads();
        float var = (sRed[4] + sRed[5] + sRed[6] + sRed[7]) * (1.0f / H);
        g_hV1[(size_t)(p0 + n) * H + tid] = d * rsqrtf(var + 1e-5f) * g1[tid] + be1[tid];
        __syncthreads();
    }
}

// ---------------- kernel 3: edge update MLP (mma.sync tf32) + LN3 ----------------
__global__ void __launch_bounds__(128, 2)
edge_mma_kernel(const float* __restrict__ hE,
                const float* __restrict__ b12, const float* __restrict__ b13,
                const float* __restrict__ g3, const float* __restrict__ be3,
                const int* __restrict__ Eidx, float* __restrict__ outE) {
    extern __shared__ float smf[];
    float* sX   = smf;
    float* sW   = smf + 16896;
    float* sD   = smf + 25600;
    int*   sIdx = (int*)(smf + 27648);

    const int tid = threadIdx.x;
    const int wid = tid >> 5, lane = tid & 31;
    const int p0 = blockIdx.x * 8;
    const int bb = p0 >> 11;

    for (int i = tid; i < 8 * H; i += 128) sD[i] = g_D2[(size_t)p0 * H + i];
    for (int i = tid; i < 8 * KNB; i += 128) sIdx[i] = Eidx[(size_t)p0 * KNB + i];

    float acc[2][16][4];

    for (int t = 0; t < 3; t++) {
        const int e0 = p0 * KNB + t * 128;
        const float* arow = hE + (size_t)(e0 + tid) * H;
        float* xr = sX + tid * XP;

        __syncthreads();
#pragma unroll 8
        for (int c = 0; c < 128; c += 4) {
            float4 v = *(const float4*)(arow + c);
            xr[c + 0] = to_tf32(v.x); xr[c + 1] = to_tf32(v.y);
            xr[c + 2] = to_tf32(v.z); xr[c + 3] = to_tf32(v.w);
        }

        zero_acc(acc);
        gemm_mma(sX, sW, g_Wt + 3 * H * H, tid, acc);
        __syncthreads();
        store_acc(sX, tid, acc);
        __syncthreads();
        {
            const int src = sIdx[t * 128 + tid];
            const int nl = (t * 128 + tid) / KNB;
            const float* pr = g_P2 + ((size_t)bb * NN + src) * H;
            const float* dn = sD + nl * H;
#pragma unroll 8
            for (int c = 0; c < 128; c += 4) {
                float4 x = *(float4*)(xr + c);
                float4 p = *(const float4*)(pr + c);
                xr[c + 0] = to_tf32(gelu_exact(x.x + dn[c + 0] + p.x));
                xr[c + 1] = to_tf32(gelu_exact(x.y + dn[c + 1] + p.y));
                xr[c + 2] = to_tf32(gelu_exact(x.z + dn[c + 2] + p.z));
                xr[c + 3] = to_tf32(gelu_exact(x.w + dn[c + 3] + p.w));
            }
        }

        zero_acc(acc);
        gemm_mma(sX, sW, g_Wt + 4 * H * H, tid, acc);
        __syncthreads();
        store_acc(sX, tid, acc);
        __syncthreads();
#pragma unroll 8
        for (int c = 0; c < 128; c += 4) {
            float4 x = *(float4*)(xr + c);
            float4 bv = *(const float4*)(b12 + c);
            xr[c + 0] = to_tf32(gelu_exact(x.x + bv.x));
            xr[c + 1] = to_tf32(gelu_exact(x.y + bv.y));
            xr[c + 2] = to_tf32(gelu_exact(x.z + bv.z));
            xr[c + 3] = to_tf32(gelu_exact(x.w + bv.w));
        }

        zero_acc(acc);
        gemm_mma(sX, sW, g_Wt + 5 * H * H, tid, acc);
        __syncthreads();
        store_acc(sX, tid, acc);
        __syncthreads();
        // epi3: u = x + b13 + hE residual
#pragma unroll 8
        for (int c = 0; c < 128; c += 4) {
            float4 x = *(float4*)(xr + c);
            float4 bv = *(const float4*)(b13 + c);
            float4 ev = *(const float4*)(arow + c);
            xr[c + 0] = x.x + bv.x + ev.x;
            xr[c + 1] = x.y + bv.y + ev.y;
            xr[c + 2] = x.z + bv.z + ev.z;
            xr[c + 3] = x.w + bv.w + ev.w;
        }
        __syncthreads();

        // per-edge LN3: warp per row
        for (int r = wid * 32; r < wid * 32 + 32; r++) {
            float v[4];
            float ssum = 0.f;
#pragma unroll
            for (int q = 0; q < 4; q++) {
                v[q] = sX[r * XP + lane + 32 * q];
                ssum += v[q];
            }
#pragma unroll
            for (int off = 16; off > 0; off >>= 1) ssum += __shfl_xor_sync(0xffffffffu, ssum, off);
            float mean = ssum * (1.0f / H);
            float vs = 0.f;
#pragma unroll
            for (int q = 0; q < 4; q++) { v[q] -= mean; vs += v[q] * v[q]; }
#pragma unroll
            for (int off = 16; off > 0; off >>= 1) vs += __shfl_xor_sync(0xffffffffu, vs, off);
            float rs = rsqrtf(vs * (1.0f / H) + 1e-5f);
#pragma unroll
            for (int q = 0; q < 4; q++) {
                int c = lane + 32 * q;
                outE[(size_t)(e0 + r) * H + c] = v[q] * rs * g3[c] + be3[c];
            }
        }
    }
}

// ---------------- kernel 2: FFN + LN2 + mask_V (4 nodes/block) ----------------
__global__ void __launch_bounds__(128)
ffn_kernel(const float* __restrict__ W_in, const float* __restrict__ b_in,
           const float* __restrict__ W_out, const float* __restrict__ b_out,
           const float* __restrict__ g2, const float* __restrict__ be2,
           const float* __restrict__ maskV, float* __restrict__ outV) {
    __shared__ float sx[4 * H];
    __shared__ float sh[4 * 512];
    __shared__ float sRed[8];
    const int tid = threadIdx.x;
    const int p0 = blockIdx.x * 4;

    for (int i = tid; i < 4 * H; i += 128) sx[i] = g_hV1[(size_t)p0 * H + i];
    __syncthreads();

    float4 acc[4];
#pragma unroll
    for (int n = 0; n < 4; n++) acc[n] = make_float4(0.f, 0.f, 0.f, 0.f);

#pragma unroll 2
    for (int k = 0; k < H; k++) {
        float4 w = *(const float4*)&W_in[k * 512 + tid * 4];
#pragma unroll
        for (int n = 0; n < 4; n++) {
            float xv = sx[n * H + k];
            acc[n].x = fmaf(w.x, xv, acc[n].x);
            acc[n].y = fmaf(w.y, xv, acc[n].y);
            acc[n].z = fmaf(w.z, xv, acc[n].z);
            acc[n].w = fmaf(w.w, xv, acc[n].w);
        }
    }
    {
        float4 bi = *(const float4*)&b_in[tid * 4];
#pragma unroll
        for (int n = 0; n < 4; n++) {
            sh[n * 512 + tid * 4 + 0] = gelu_exact(acc[n].x + bi.x);
            sh[n * 512 + tid * 4 + 1] = gelu_exact(acc[n].y + bi.y);
            sh[n * 512 + tid * 4 + 2] = gelu_exact(acc[n].z + bi.z);
            sh[n * 512 + tid * 4 + 3] = gelu_exact(acc[n].w + bi.w);
        }
    }
    __syncthreads();

    float o[4] = {0.f, 0.f, 0.f, 0.f};
#pragma unroll 4
    for (int k = 0; k < 512; k++) {
        float w = W_out[k * H + tid];
#pragma unroll
        for (int n = 0; n < 4; n++) o[n] = fmaf(w, sh[n * 512 + k], o[n]);
    }

    float bo = b_out[tid];
    for (int n = 0; n < 4; n++) {
        float u = sx[n * H + tid] + o[n] + bo;
        float s = u;
#pragma unroll
        for (int off = 16; off > 0; off >>= 1) s += __shfl_xor_sync(0xffffffffu, s, off);
        if ((tid & 31) == 0) sRed[tid >> 5] = s;
        __syncthreads();
        float mean = (sRed[0] + sRed[1] + sRed[2] + sRed[3]) * (1.0f / H);
        float d = u - mean;
        float v2 = d * d;
#pragma unroll
        for (int off = 16; off > 0; off >>= 1) v2 += __shfl_xor_sync(0xffffffffu, v2, off);
        if ((tid & 31) == 0) sRed[4 + (tid >> 5)] = v2;
        __syncthreads();
        float var = (sRed[4] + sRed[5] + sRed[6] + sRed[7]) * (1.0f / H);
        float res = (d * rsqrtf(var + 1e-5f) * g2[tid] + be2[tid]) * maskV[p0 + n];
        outV[(size_t)(p0 + n) * H + tid] = res;
        __syncthreads();
    }
}

// ---------------- launch ----------------
extern "C" void kernel_launch(void* const* d_in, const int* in_sizes, int n_in,
                              void* d_out, int out_size) {
    const float* hV    = (const float*)d_in[0];
    const float* hVa   = (const float*)d_in[1];
    const float* hE    = (const float*)d_in[2];
    const float* W1    = (const float*)d_in[3];
    const float* b1    = (const float*)d_in[4];
    const float* W2    = (const float*)d_in[5];
    const float* b2    = (const float*)d_in[6];
    const float* W3    = (const float*)d_in[7];
    const float* b3    = (const float*)d_in[8];
    const float* W11   = (const float*)d_in[9];
    const float* b11   = (const float*)d_in[10];
    const float* W12   = (const float*)d_in[11];
    const float* b12   = (const float*)d_in[12];
    const float* W13   = (const float*)d_in[13];
    const float* b13   = (const float*)d_in[14];
    const float* W_in  = (const float*)d_in[15];
    const float* b_in  = (const float*)d_in[16];
    const float* W_out = (const float*)d_in[17];
    const float* b_out = (const float*)d_in[18];
    const float* g1    = (const float*)d_in[19];
    const float* be1   = (const float*)d_in[20];
    const float* g2    = (const float*)d_in[21];
    const float* be2   = (const float*)d_in[22];
    const float* g3    = (const float*)d_in[23];
    const float* be3   = (const float*)d_in[24];
    const float* maskV = (const float*)d_in[25];
    const float* maskA = (const float*)d_in[26];
    const int*   Eidx  = (const int*)d_in[27];

    const int BN = in_sizes[0] / H;   // 4096
    float* outV = (float*)d_out;
    float* outE = (float*)d_out + (size_t)BN * H;

    const size_t smemN = SMEMN_FLOATS * sizeof(float);   // ~109.6 KB
    const size_t smemE = SMEME_FLOATS * sizeof(float);

    cudaFuncSetAttribute(node_mma_kernel, cudaFuncAttributeMaxDynamicSharedMemorySize, (int)smemN);
    cudaFuncSetAttribute(edge_mma_kernel, cudaFuncAttributeMaxDynamicSharedMemorySize, (int)smemE);

    prep_weights<<<(6 * H * H + 255) / 256, 256>>>(W1, W2, W3, W11, W12, W13);
    pre1_kernel<<<BN / 8, 128>>>(hV, hVa, W1, b1);
    node_mma_kernel<<<BN / 8, 128, smemN>>>(hV, hE, b2, b3, g1, be1, maskA, Eidx);
    ffn_kernel<<<BN / 4, 128>>>(W_in, b_in, W_out, b_out, g2, be2, maskV, outV);
    pre2_kernel<<<BN / 8, 128>>>(outV, W11, b11);
    edge_mma_kernel<<<BN / 8, 128, smemE>>>(hE, b12, b13, g3, be3, Eidx, outE);
}

// round 6
// speedup vs baseline: 2.8231x; 1.0972x over previous
#include <cuda_runtime.h>
#include <cstdint>
#include <math.h>

#define H      128
#define HH     (H * H)
#define KNB    48
#define NN     2048
#define BNTOT  4096
#define XP     132          // activation tile pitch (floats)
#define WP     68           // weight tile pitch (floats)

// weight matrix slots in g_Wt (all 128x128 [n][k], tf32-rounded)
#define W_E1   0
#define W_2T   1
#define W_3T   2
#define W_11E  3
#define W_12T  4
#define W_13T  5
#define W_1V   6
#define W_1G   7
#define W_1A   8
#define W_11V  9
#define W_11G  10
#define W_INT  11   // 11..14: W_in^T chunks (n = hidden nc*128+..)
#define W_OUTT 15   // 15..18: W_out^T chunks (k = hidden kc*128+..)

__device__ float g_Wt[19 * HH];
__device__ float g_D1[BNTOT * H];
__device__ float g_P1[BNTOT * H];
__device__ float g_D2[BNTOT * H];
__device__ float g_P2[BNTOT * H];
__device__ float g_hV1[BNTOT * H];

__device__ __forceinline__ float to_tf32(float x) {
    uint32_t u;
    asm("cvt.rna.tf32.f32 %0, %1;" : "=r"(u) : "f"(x));
    return __uint_as_float(u);
}

__device__ __forceinline__ float gelu_exact(float x) {
    return 0.5f * x * (1.0f + erff(x * 0.70710678118654752f));
}

__device__ __forceinline__ void mma_tf32(float d[4], const uint32_t a[4], const uint32_t b[2]) {
    asm volatile("mma.sync.aligned.m16n8k8.row.col.f32.tf32.tf32.f32 "
                 "{%0,%1,%2,%3}, {%4,%5,%6,%7}, {%8,%9}, {%0,%1,%2,%3};"
                 : "+f"(d[0]), "+f"(d[1]), "+f"(d[2]), "+f"(d[3])
                 : "r"(a[0]), "r"(a[1]), "r"(a[2]), "r"(a[3]), "r"(b[0]), "r"(b[1]));
}

// ---------------- 128x128x128 tf32 GEMM, 256 threads (8 warps, 4m x 2n grid) ----------------
// warp tile 32 rows x 64 cols; acc[2][8][4]. Accumulates into acc (no zeroing).
__device__ __forceinline__ void gemm256(const float* __restrict__ sX, float* __restrict__ sW,
                                        const float* __restrict__ Wg, int tid,
                                        float acc[2][8][4]) {
    const int w = tid >> 5, lane = tid & 31;
    const int wm = w & 3, wn = w >> 2;
    const int lr = lane >> 2, lc = lane & 3;
    const float* sXw = sX + (wm * 32 + lr) * XP + lc;
    const float* sWb = sW + (wn * 64 + lr) * WP + lc;
#pragma unroll
    for (int h = 0; h < 2; h++) {
        __syncthreads();                      // prior consumers done; sX producer writes done
#pragma unroll
        for (int i = 0; i < 8; i++) {
            int idx = tid + 256 * i;          // 2048 float4 per 64-k half
            int n = idx >> 4, q = idx & 15;
            float4 v = *(const float4*)(Wg + n * H + h * 64 + q * 4);
            *(float4*)(sW + n * WP + q * 4) = v;
        }
        __syncthreads();
#pragma unroll
        for (int k8 = 0; k8 < 8; k8++) {
            const int kl = k8 * 8;
            uint32_t a[2][4];
#pragma unroll
            for (int mt = 0; mt < 2; mt++) {
                const float* ap = sXw + mt * (16 * XP) + h * 64 + kl;
                a[mt][0] = __float_as_uint(ap[0]);
                a[mt][1] = __float_as_uint(ap[8 * XP]);
                a[mt][2] = __float_as_uint(ap[4]);
                a[mt][3] = __float_as_uint(ap[8 * XP + 4]);
            }
#pragma unroll
            for (int nt = 0; nt < 8; nt++) {
                const float* bp = sWb + nt * (8 * WP) + kl;
                uint32_t b[2];
                b[0] = __float_as_uint(bp[0]);
                b[1] = __float_as_uint(bp[4]);
                mma_tf32(acc[0][nt], a[0], b);
                mma_tf32(acc[1][nt], a[1], b);
            }
        }
    }
}

__device__ __forceinline__ void zero_acc(float acc[2][8][4]) {
#pragma unroll
    for (int mt = 0; mt < 2; mt++)
#pragma unroll
        for (int nt = 0; nt < 8; nt++)
#pragma unroll
            for (int q = 0; q < 4; q++) acc[mt][nt][q] = 0.f;
}

// plain fp32 store of acc into a pitched tile
__device__ __forceinline__ void store_acc(float* __restrict__ dst, int tid,
                                          const float acc[2][8][4]) {
    const int w = tid >> 5, lane = tid & 31;
    const int wm = w & 3, wn = w >> 2;
    const int lr = lane >> 2, lc = lane & 3;
    float* cx = dst + (wm * 32 + lr) * XP + wn * 64 + 2 * lc;
#pragma unroll
    for (int mt = 0; mt < 2; mt++)
#pragma unroll
        for (int nt = 0; nt < 8; nt++) {
            *(float2*)(cx + mt * (16 * XP) + nt * 8) =
                make_float2(acc[mt][nt][0], acc[mt][nt][1]);
            *(float2*)(cx + mt * (16 * XP) + 8 * XP + nt * 8) =
                make_float2(acc[mt][nt][2], acc[mt][nt][3]);
        }
}

// register epilogue: dst = to_tf32(gelu(acc + bias[col]))
__device__ __forceinline__ void epi_bias_gelu(float* __restrict__ dst, int tid,
                                              const float acc[2][8][4],
                                              const float* __restrict__ bias) {
    const int w = tid >> 5, lane = tid & 31;
    const int wm = w & 3, wn = w >> 2;
    const int lr = lane >> 2, lc = lane & 3;
    float* cx = dst + (wm * 32 + lr) * XP + wn * 64 + 2 * lc;
#pragma unroll
    for (int nt = 0; nt < 8; nt++) {
        float2 bv = *(const float2*)(bias + wn * 64 + nt * 8 + 2 * lc);
#pragma unroll
        for (int mt = 0; mt < 2; mt++) {
            *(float2*)(cx + mt * (16 * XP) + nt * 8) =
                make_float2(to_tf32(gelu_exact(acc[mt][nt][0] + bv.x)),
                            to_tf32(gelu_exact(acc[mt][nt][1] + bv.y)));
            *(float2*)(cx + mt * (16 * XP) + 8 * XP + nt * 8) =
                make_float2(to_tf32(gelu_exact(acc[mt][nt][2] + bv.x)),
                            to_tf32(gelu_exact(acc[mt][nt][3] + bv.y)));
        }
    }
}

// register epilogue: dst = mask[row] * (acc + bias[col])   (fp32)
__device__ __forceinline__ void epi_mask_bias(float* __restrict__ dst, int tid,
                                              const float acc[2][8][4],
                                              const float* __restrict__ bias,
                                              const float* __restrict__ sMask) {
    const int w = tid >> 5, lane = tid & 31;
    const int wm = w & 3, wn = w >> 2;
    const int lr = lane >> 2, lc = lane & 3;
    float* cx = dst + (wm * 32 + lr) * XP + wn * 64 + 2 * lc;
#pragma unroll
    for (int mt = 0; mt < 2; mt++) {
        int r0 = wm * 32 + mt * 16 + lr;
        float mk0 = sMask[r0], mk8 = sMask[r0 + 8];
#pragma unroll
        for (int nt = 0; nt < 8; nt++) {
            float2 bv = *(const float2*)(bias + wn * 64 + nt * 8 + 2 * lc);
            *(float2*)(cx + mt * (16 * XP) + nt * 8) =
                make_float2(mk0 * (acc[mt][nt][0] + bv.x), mk0 * (acc[mt][nt][1] + bv.y));
            *(float2*)(cx + mt * (16 * XP) + 8 * XP + nt * 8) =
                make_float2(mk8 * (acc[mt][nt][2] + bv.x), mk8 * (acc[mt][nt][3] + bv.y));
        }
    }
}

// register epilogue: global[row][col] = acc + optional bias (fp32), rows offset p0
__device__ __forceinline__ void epi_to_global(float* __restrict__ gdst, int p0, int tid,
                                              const float acc[2][8][4],
                                              const float* __restrict__ bias) {
    const int w = tid >> 5, lane = tid & 31;
    const int wm = w & 3, wn = w >> 2;
    const int lr = lane >> 2, lc = lane & 3;
#pragma unroll
    for (int nt = 0; nt < 8; nt++) {
        int col = wn * 64 + nt * 8 + 2 * lc;
        float2 bv = bias ? *(const float2*)(bias + col) : make_float2(0.f, 0.f);
#pragma unroll
        for (int mt = 0; mt < 2; mt++) {
            int r0 = wm * 32 + mt * 16 + lr;
            *(float2*)(gdst + (size_t)(p0 + r0) * H + col) =
                make_float2(acc[mt][nt][0] + bv.x, acc[mt][nt][1] + bv.y);
            *(float2*)(gdst + (size_t)(p0 + r0 + 8) * H + col) =
                make_float2(acc[mt][nt][2] + bv.x, acc[mt][nt][3] + bv.y);
        }
    }
}

// ---------------- prep: all transposed/folded weights, tf32-rounded ----------------
__global__ void prep_weights(const float* __restrict__ W1, const float* __restrict__ W2,
                             const float* __restrict__ W3, const float* __restrict__ W11,
                             const float* __restrict__ W12, const float* __restrict__ W13,
                             const float* __restrict__ W_in, const float* __restrict__ W_out) {
    int idx = blockIdx.x * 256 + threadIdx.x;
    if (idx >= 19 * HH) return;
    int m = idx / HH;
    int r = (idx >> 7) & 127;   // n
    int c = idx & 127;          // k
    float v;
    switch (m) {
        case W_E1:  v = W1[(128 + c) * H + r] + W1[(384 + c) * H + r]; break;
        case W_2T:  v = W2[c * H + r]; break;
        case W_3T:  v = W3[c * H + r]; break;
        case W_11E: v = W11[(128 + c) * H + r]; break;
        case W_12T: v = W12[c * H + r]; break;
        case W_13T: v = W13[c * H + r]; break;
        case W_1V:  v = W1[c * H + r]; break;
        case W_1G:  v = W1[(256 + c) * H + r]; break;
        case W_1A:  v = W1[(512 + c) * H + r]; break;
        case W_11V: v = W11[c * H + r]; break;
        case W_11G: v = W11[(256 + c) * H + r]; break;
        default:
            if (m < W_OUTT) {                 // W_in^T chunk nc = m-11
                int nc = m - W_INT;
                v = W_in[c * 512 + nc * 128 + r];
            } else {                          // W_out^T chunk kc = m-15
                int kc = m - W_OUTT;
                v = W_out[(kc * 128 + c) * H + r];
            }
            break;
    }
    g_Wt[idx] = to_tf32(v);
}

// ---------------- pre1: D1 = hV@W1v + b1 ; P1 = hV@W1g + hVa@W1a ----------------
// smem: sXa 16896 | sXb 16896 | sW 8704
__global__ void __launch_bounds__(256)
pre1_mma(const float* __restrict__ hV, const float* __restrict__ hVa,
         const float* __restrict__ b1) {
    extern __shared__ float smf[];
    float* sXa = smf;
    float* sXb = smf + 16896;
    float* sW  = smf + 33792;
    const int tid = threadIdx.x;
    const int p0 = blockIdx.x * 128;
    const int r = tid >> 1, ch = (tid & 1) * 64;

    {
        const float* a = hV + (size_t)(p0 + r) * H + ch;
        const float* b = hVa + (size_t)(p0 + r) * H + ch;
        float* xa = sXa + r * XP + ch;
        float* xb = sXb + r * XP + ch;
#pragma unroll
        for (int c = 0; c < 64; c += 4) {
            float4 v = *(const float4*)(a + c);
            xa[c] = to_tf32(v.x); xa[c+1] = to_tf32(v.y); xa[c+2] = to_tf32(v.z); xa[c+3] = to_tf32(v.w);
            float4 u = *(const float4*)(b + c);
            xb[c] = to_tf32(u.x); xb[c+1] = to_tf32(u.y); xb[c+2] = to_tf32(u.z); xb[c+3] = to_tf32(u.w);
        }
    }

    float acc[2][8][4];
    zero_acc(acc);
    gemm256(sXa, sW, g_Wt + W_1V * HH, tid, acc);
    epi_to_global(g_D1, p0, tid, acc, b1);

    zero_acc(acc);
    gemm256(sXa, sW, g_Wt + W_1G * HH, tid, acc);
    gemm256(sXb, sW, g_Wt + W_1A * HH, tid, acc);
    epi_to_global(g_P1, p0, tid, acc, (const float*)nullptr);
}

// ---------------- pre2: D2 = hVf@W11v + b11 ; P2 = hVf@W11g ----------------
__global__ void __launch_bounds__(256)
pre2_mma(const float* __restrict__ hVf, const float* __restrict__ b11) {
    extern __shared__ float smf[];
    float* sXa = smf;
    float* sW  = smf + 33792;
    const int tid = threadIdx.x;
    const int p0 = blockIdx.x * 128;
    const int r = tid >> 1, ch = (tid & 1) * 64;

    {
        const float* a = hVf + (size_t)(p0 + r) * H + ch;
        float* xa = sXa + r * XP + ch;
#pragma unroll
        for (int c = 0; c < 64; c += 4) {
            float4 v = *(const float4*)(a + c);
            xa[c] = to_tf32(v.x); xa[c+1] = to_tf32(v.y); xa[c+2] = to_tf32(v.z); xa[c+3] = to_tf32(v.w);
        }
    }

    float acc[2][8][4];
    zero_acc(acc);
    gemm256(sXa, sW, g_Wt + W_11V * HH, tid, acc);
    epi_to_global(g_D2, p0, tid, acc, b11);

    zero_acc(acc);
    gemm256(sXa, sW, g_Wt + W_11G * HH, tid, acc);
    epi_to_global(g_P2, p0, tid, acc, (const float*)nullptr);
}

// node/edge smem layout (floats):
//  sX 0..16896 | sW 16896..25600 (alias sAcc2 2048) | sD 25600..26624 |
//  sAcc 26624..27648 | sIdx 27648..28032 (int) | sMask 28032..28160 | sRed 28160..28176
#define SMEM_MLP 28176

// ---------------- node message MLP + sum_K + LN1 ----------------
__global__ void __launch_bounds__(256, 2)
node_mma_kernel(const float* __restrict__ hV, const float* __restrict__ hE,
                const float* __restrict__ b2, const float* __restrict__ b3,
                const float* __restrict__ g1, const float* __restrict__ be1,
                const float* __restrict__ maskA, const int* __restrict__ Eidx) {
    extern __shared__ float smf[];
    float* sX    = smf;
    float* sW    = smf + 16896;
    float* sAcc2 = sW;                         // alias (8KB, used after GEMM3)
    float* sD    = smf + 25600;
    float* sAcc  = smf + 26624;
    int*   sIdx  = (int*)(smf + 27648);
    float* sMask = smf + 28032;
    float* sRed  = smf + 28160;

    const int tid = threadIdx.x;
    const int p0 = blockIdx.x * 8;
    const int bb = p0 >> 11;
    const int r = tid >> 1, ch = (tid & 1) * 64;

    for (int i = tid; i < 8 * H; i += 256) {
        sD[i] = g_D1[(size_t)p0 * H + i];
        sAcc[i] = 0.f;
    }
    for (int i = tid; i < 8 * KNB; i += 256) sIdx[i] = Eidx[(size_t)p0 * KNB + i];

    float acc[2][8][4];

    for (int t = 0; t < 3; t++) {
        const int e0 = p0 * KNB + t * 128;
        float* xr = sX + r * XP + ch;

        __syncthreads();                       // prior tile fully consumed
        {
            const float* a = hE + (size_t)(e0 + r) * H + ch;
#pragma unroll
            for (int c = 0; c < 64; c += 4) {
                float4 v = *(const float4*)(a + c);
                xr[c] = to_tf32(v.x); xr[c+1] = to_tf32(v.y);
                xr[c+2] = to_tf32(v.z); xr[c+3] = to_tf32(v.w);
            }
        }
        if (tid < 128) sMask[tid] = maskA[e0 + tid];

        // ---- GEMM1 + epi1 (smem: needs per-row gather P1) ----
        zero_acc(acc);
        gemm256(sX, sW, g_Wt + W_E1 * HH, tid, acc);
        __syncthreads();
        store_acc(sX, tid, acc);
        __syncthreads();
        {
            const int src = sIdx[t * 128 + r];
            const int nl = (t * 128 + r) / KNB;
            const float* pr = g_P1 + ((size_t)bb * NN + src) * H + ch;
            const float* dn = sD + nl * H + ch;
#pragma unroll
            for (int c = 0; c < 64; c += 4) {
                float4 x = *(float4*)(xr + c);
                float4 p = *(const float4*)(pr + c);
                xr[c]   = to_tf32(gelu_exact(x.x + dn[c]   + p.x));
                xr[c+1] = to_tf32(gelu_exact(x.y + dn[c+1] + p.y));
                xr[c+2] = to_tf32(gelu_exact(x.z + dn[c+2] + p.z));
                xr[c+3] = to_tf32(gelu_exact(x.w + dn[c+3] + p.w));
            }
        }

        // ---- GEMM2 + register epi2 ----
        zero_acc(acc);
        gemm256(sX, sW, g_Wt + W_2T * HH, tid, acc);
        __syncthreads();
        epi_bias_gelu(sX, tid, acc, b2);

        // ---- GEMM3 + register epi3 (mask) ----
        zero_acc(acc);
        gemm256(sX, sW, g_Wt + W_3T * HH, tid, acc);
        __syncthreads();
        epi_mask_bias(sX, tid, acc, b3, sMask);
        for (int i = tid; i < 2048; i += 256) sAcc2[i] = 0.f;
        __syncthreads();

        // ---- segment-sum: rows -> per-node partials ----
        {
            const int col = tid & 127, half = tid >> 7;
            int rr = half * 64;
            int nl = (t * 128 + rr) / KNB;
            int nxt = (nl + 1) * KNB - t * 128;
            float a = 0.f;
            for (; rr < half * 64 + 64; rr++) {
                if (rr == nxt) { sAcc2[half * 1024 + nl * 128 + col] = a; nl++; nxt += KNB; a = 0.f; }
                a += sX[rr * XP + col];
            }
            sAcc2[half * 1024 + nl * 128 + col] = a;
        }
        __syncthreads();
        for (int i = tid; i < 1024; i += 256)
            sAcc[i] += sAcc2[i] + sAcc2[1024 + i];
    }
    __syncthreads();

    // ---- LN1: 2 nodes at a time ----
    for (int step = 0; step < 4; step++) {
        const int g = tid >> 7;
        const int n = step * 2 + g;
        const int c = tid & 127;
        float u = hV[(size_t)(p0 + n) * H + c] + sAcc[n * 128 + c] * (1.0f / 30.0f);
        float s = u;
#pragma unroll
        for (int off = 16; off > 0; off >>= 1) s += __shfl_xor_sync(0xffffffffu, s, off);
        if ((tid & 31) == 0) sRed[tid >> 5] = s;
        __syncthreads();
        float mean = (sRed[g*4] + sRed[g*4+1] + sRed[g*4+2] + sRed[g*4+3]) * (1.0f / H);
        float d = u - mean;
        float v2 = d * d;
#pragma unroll
        for (int off = 16; off > 0; off >>= 1) v2 += __shfl_xor_sync(0xffffffffu, v2, off);
        if ((tid & 31) == 0) sRed[8 + (tid >> 5)] = v2;
        __syncthreads();
        float var = (sRed[8+g*4] + sRed[8+g*4+1] + sRed[8+g*4+2] + sRed[8+g*4+3]) * (1.0f / H);
        g_hV1[(size_t)(p0 + n) * H + c] = d * rsqrtf(var + 1e-5f) * g1[c] + be1[c];
        __syncthreads();
    }
}

// ---------------- edge update MLP + LN3 ----------------
__global__ void __launch_bounds__(256, 2)
edge_mma_kernel(const float* __restrict__ hE,
                const float* __restrict__ b12, const float* __restrict__ b13,
                const float* __restrict__ g3, const float* __restrict__ be3,
                const int* __restrict__ Eidx, float* __restrict__ outE) {
    extern __shared__ float smf[];
    float* sX   = smf;
    float* sW   = smf + 16896;
    float* sD   = smf + 25600;
    int*   sIdx = (int*)(smf + 27648);

    const int tid = threadIdx.x;
    const int w = tid >> 5, lane = tid & 31;
    const int p0 = blockIdx.x * 8;
    const int bb = p0 >> 11;
    const int r = tid >> 1, ch = (tid & 1) * 64;

    for (int i = tid; i < 8 * H; i += 256) sD[i] = g_D2[(size_t)p0 * H + i];
    for (int i = tid; i < 8 * KNB; i += 256) sIdx[i] = Eidx[(size_t)p0 * KNB + i];

    float acc[2][8][4];

    for (int t = 0; t < 3; t++) {
        const int e0 = p0 * KNB + t * 128;
        float* xr = sX + r * XP + ch;
        const float* arow = hE + (size_t)(e0 + r) * H + ch;

        __syncthreads();
#pragma unroll
        for (int c = 0; c < 64; c += 4) {
            float4 v = *(const float4*)(arow + c);
            xr[c] = to_tf32(v.x); xr[c+1] = to_tf32(v.y);
            xr[c+2] = to_tf32(v.z); xr[c+3] = to_tf32(v.w);
        }

        zero_acc(acc);
        gemm256(sX, sW, g_Wt + W_11E * HH, tid, acc);
        __syncthreads();
        store_acc(sX, tid, acc);
        __syncthreads();
        {
            const int src = sIdx[t * 128 + r];
            const int nl = (t * 128 + r) / KNB;
            const float* pr = g_P2 + ((size_t)bb * NN + src) * H + ch;
            const float* dn = sD + nl * H + ch;
#pragma unroll
            for (int c = 0; c < 64; c += 4) {
                float4 x = *(float4*)(xr + c);
                float4 p = *(const float4*)(pr + c);
                xr[c]   = to_tf32(gelu_exact(x.x + dn[c]   + p.x));
                xr[c+1] = to_tf32(gelu_exact(x.y + dn[c+1] + p.y));
                xr[c+2] = to_tf32(gelu_exact(x.z + dn[c+2] + p.z));
                xr[c+3] = to_tf32(gelu_exact(x.w + dn[c+3] + p.w));
            }
        }

        zero_acc(acc);
        gemm256(sX, sW, g_Wt + W_12T * HH, tid, acc);
        __syncthreads();
        epi_bias_gelu(sX, tid, acc, b12);

        zero_acc(acc);
        gemm256(sX, sW, g_Wt + W_13T * HH, tid, acc);
        __syncthreads();
        store_acc(sX, tid, acc);
        __syncthreads();
        // epi3: u = x + b13 + hE residual (fp32)
#pragma unroll
        for (int c = 0; c < 64; c += 4) {
            float4 x = *(float4*)(xr + c);
            float4 bv = *(const float4*)(b13 + ch + c);
            float4 ev = *(const float4*)(arow + c);
            xr[c]   = x.x + bv.x + ev.x;
            xr[c+1] = x.y + bv.y + ev.y;
            xr[c+2] = x.z + bv.z + ev.z;
            xr[c+3] = x.w + bv.w + ev.w;
        }
        __syncthreads();

        // LN3: each warp 16 rows
        for (int rr = w * 16; rr < w * 16 + 16; rr++) {
            float v[4];
            float ssum = 0.f;
#pragma unroll
            for (int q = 0; q < 4; q++) {
                v[q] = sX[rr * XP + lane + 32 * q];
                ssum += v[q];
            }
#pragma unroll
            for (int off = 16; off > 0; off >>= 1) ssum += __shfl_xor_sync(0xffffffffu, ssum, off);
            float mean = ssum * (1.0f / H);
            float vs = 0.f;
#pragma unroll
            for (int q = 0; q < 4; q++) { v[q] -= mean; vs += v[q] * v[q]; }
#pragma unroll
            for (int off = 16; off > 0; off >>= 1) vs += __shfl_xor_sync(0xffffffffu, vs, off);
            float rs = rsqrtf(vs * (1.0f / H) + 1e-5f);
#pragma unroll
            for (int q = 0; q < 4; q++) {
                int c = lane + 32 * q;
                outE[(size_t)(e0 + rr) * H + c] = v[q] * rs * g3[c] + be3[c];
            }
        }
    }
}

// ---------------- FFN (tensor): 128 nodes/CTA, grid 32 ----------------
// smem: sXa 16896 | sXb 16896 | sW 8704 | sRedA 256
__global__ void __launch_bounds__(256)
ffn_mma(const float* __restrict__ b_in, const float* __restrict__ b_out,
        const float* __restrict__ g2, const float* __restrict__ be2,
        const float* __restrict__ maskV, float* __restrict__ outV) {
    extern __shared__ float smf[];
    float* sXa   = smf;
    float* sXb   = smf + 16896;
    float* sW    = smf + 33792;
    float* sRedA = smf + 42496;
    const int tid = threadIdx.x;
    const int p0 = blockIdx.x * 128;
    const int r = tid >> 1, ch = (tid & 1) * 64;

    {
        const float* a = g_hV1 + (size_t)(p0 + r) * H + ch;
        float* xa = sXa + r * XP + ch;
#pragma unroll
        for (int c = 0; c < 64; c += 4) {
            float4 v = *(const float4*)(a + c);
            xa[c] = to_tf32(v.x); xa[c+1] = to_tf32(v.y);
            xa[c+2] = to_tf32(v.z); xa[c+3] = to_tf32(v.w);
        }
    }

    float acc[2][8][4], acc2[2][8][4];
    zero_acc(acc2);
#pragma unroll
    for (int nc = 0; nc < 4; nc++) {
        zero_acc(acc);
        gemm256(sXa, sW, g_Wt + (W_INT + nc) * HH, tid, acc);
        __syncthreads();
        epi_bias_gelu(sXb, tid, acc, b_in + nc * 128);
        gemm256(sXb, sW, g_Wt + (W_OUTT + nc) * HH, tid, acc2);
    }
    __syncthreads();
    store_acc(sXb, tid, acc2);
    __syncthreads();

    // LN2 + maskV; residual from g_hV1 (fp32)
    float* xr = sXb + r * XP + ch;
    {
        const float* res = g_hV1 + (size_t)(p0 + r) * H + ch;
        float s = 0.f;
#pragma unroll
        for (int c = 0; c < 64; c += 4) {
            float4 x = *(float4*)(xr + c);
            float4 rv = *(const float4*)(res + c);
            float4 bo = *(const float4*)(b_out + ch + c);
            x.x += rv.x + bo.x; x.y += rv.y + bo.y;
            x.z += rv.z + bo.z; x.w += rv.w + bo.w;
            *(float4*)(xr + c) = x;
            s += x.x + x.y + x.z + x.w;
        }
        sRedA[tid] = s;
    }
    __syncthreads();
    float mean = (sRedA[tid] + sRedA[tid ^ 1]) * (1.0f / H);
    __syncthreads();
    {
        float v2 = 0.f;
#pragma unroll
        for (int c = 0; c < 64; c++) {
            float d = xr[c] - mean;
            v2 += d * d;
        }
        sRedA[tid] = v2;
    }
    __syncthreads();
    float var = (sRedA[tid] + sRedA[tid ^ 1]) * (1.0f / H);
    float rs = rsqrtf(var + 1e-5f);
    float mv = maskV[p0 + r];
#pragma unroll
    for (int c = 0; c < 64; c++) {
        int col = ch + c;
        outV[(size_t)(p0 + r) * H + col] =
            ((xr[c] - mean) * rs * g2[col] + be2[col]) * mv;
    }
}

// ---------------- launch ----------------
extern "C" void kernel_launch(void* const* d_in, const int* in_sizes, int n_in,
                              void* d_out, int out_size) {
    const float* hV    = (const float*)d_in[0];
    const float* hVa   = (const float*)d_in[1];
    const float* hE    = (const float*)d_in[2];
    const float* W1    = (const float*)d_in[3];
    const float* b1    = (const float*)d_in[4];
    const float* W2    = (const float*)d_in[5];
    const float* b2    = (const float*)d_in[6];
    const float* W3    = (const float*)d_in[7];
    const float* b3    = (const float*)d_in[8];
    const float* W11   = (const float*)d_in[9];
    const float* b11   = (const float*)d_in[10];
    const float* W12   = (const float*)d_in[11];
    const float* b12   = (const float*)d_in[12];
    const float* W13   = (const float*)d_in[13];
    const float* b13   = (const float*)d_in[14];
    const float* W_in  = (const float*)d_in[15];
    const float* b_in  = (const float*)d_in[16];
    const float* W_out = (const float*)d_in[17];
    const float* b_out = (const float*)d_in[18];
    const float* g1    = (const float*)d_in[19];
    const float* be1   = (const float*)d_in[20];
    const float* g2    = (const float*)d_in[21];
    const float* be2   = (const float*)d_in[22];
    const float* g3    = (const float*)d_in[23];
    const float* be3   = (const float*)d_in[24];
    const float* maskV = (const float*)d_in[25];
    const float* maskA = (const float*)d_in[26];
    const int*   Eidx  = (const int*)d_in[27];

    const int BN = in_sizes[0] / H;   // 4096
    float* outV = (float*)d_out;
    float* outE = (float*)d_out + (size_t)BN * H;

    const size_t smemMLP = SMEM_MLP * sizeof(float);        // ~110.1 KB
    const size_t smemPRE = (33792 + 8704) * sizeof(float);  // 166 KB
    const size_t smemFFN = (42496 + 256) * sizeof(float);   // 167 KB

    cudaFuncSetAttribute(node_mma_kernel, cudaFuncAttributeMaxDynamicSharedMemorySize, (int)smemMLP);
    cudaFuncSetAttribute(edge_mma_kernel, cudaFuncAttributeMaxDynamicSharedMemorySize, (int)smemMLP);
    cudaFuncSetAttribute(pre1_mma, cudaFuncAttributeMaxDynamicSharedMemorySize, (int)smemPRE);
    cudaFuncSetAttribute(pre2_mma, cudaFuncAttributeMaxDynamicSharedMemorySize, (int)smemPRE);
    cudaFuncSetAttribute(ffn_mma,  cudaFuncAttributeMaxDynamicSharedMemorySize, (int)smemFFN);

    prep_weights<<<(19 * HH + 255) / 256, 256>>>(W1, W2, W3, W11, W12, W13, W_in, W_out);
    pre1_mma<<<BN / 128, 256, smemPRE>>>(hV, hVa, b1);
    node_mma_kernel<<<BN / 8, 256, smemMLP>>>(hV, hE, b2, b3, g1, be1, maskA, Eidx);
    ffn_mma<<<BN / 128, 256, smemFFN>>>(b_in, b_out, g2, be2, maskV, outV);
    pre2_mma<<<BN / 128, 256, smemPRE>>>(outV, b11);
    edge_mma_kernel<<<BN / 8, 256, smemMLP>>>(hE, b12, b13, g3, be3, Eidx, outE);
}

// round 9
// speedup vs baseline: 3.1183x; 1.1046x over previous
#include <cuda_runtime.h>
#include <cstdint>
#include <math.h>

#define H      128
#define HH     (H * H)
#define KNB    48
#define NN     2048
#define BNTOT  4096
#define XP     132          // activation tile pitch (floats)
#define WP     68           // weight tile pitch (floats)

// weight matrix slots in g_Wt (all 128x128 [n][k], tf32-rounded)
#define W_E1   0
#define W_2T   1
#define W_3T   2
#define W_11E  3
#define W_12T  4
#define W_13T  5
#define W_1V   6
#define W_1G   7
#define W_1A   8
#define W_11V  9
#define W_11G  10
#define W_INT  11   // 11..14: W_in^T chunks
#define W_OUTT 15   // 15..18: W_out^T chunks

__device__ float g_Wt[19 * HH];
__device__ float g_D1[BNTOT * H];
__device__ float g_P1[BNTOT * H];
__device__ float g_D2[BNTOT * H];
__device__ float g_P2[BNTOT * H];
__device__ float g_hV1[BNTOT * H];

__device__ __forceinline__ float to_tf32(float x) {
    uint32_t u;
    asm("cvt.rna.tf32.f32 %0, %1;" : "=r"(u) : "f"(x));
    return __uint_as_float(u);
}

__device__ __forceinline__ float gelu_exact(float x) {
    return 0.5f * x * (1.0f + erff(x * 0.70710678118654752f));
}

__device__ __forceinline__ void mma_tf32(float d[4], const uint32_t a[4], const uint32_t b[2]) {
    asm volatile("mma.sync.aligned.m16n8k8.row.col.f32.tf32.tf32.f32 "
                 "{%0,%1,%2,%3}, {%4,%5,%6,%7}, {%8,%9}, {%0,%1,%2,%3};"
                 : "+f"(d[0]), "+f"(d[1]), "+f"(d[2]), "+f"(d[3])
                 : "r"(a[0]), "r"(a[1]), "r"(a[2]), "r"(a[3]), "r"(b[0]), "r"(b[1]));
}

// ---------------- 128x128x128 tf32 GEMM, 256 threads (8 warps, 4m x 2n) ----------------
__device__ __forceinline__ void gemm256(const float* __restrict__ sX, float* __restrict__ sW,
                                        const float* __restrict__ Wg, int tid,
                                        float acc[2][8][4]) {
    const int w = tid >> 5, lane = tid & 31;
    const int wm = w & 3, wn = w >> 2;
    const int lr = lane >> 2, lc = lane & 3;
    const float* sXw = sX + (wm * 32 + lr) * XP + lc;
    const float* sWb = sW + (wn * 64 + lr) * WP + lc;
#pragma unroll
    for (int h = 0; h < 2; h++) {
        __syncthreads();
#pragma unroll
        for (int i = 0; i < 8; i++) {
            int idx = tid + 256 * i;
            int n = idx >> 4, q = idx & 15;
            float4 v = *(const float4*)(Wg + n * H + h * 64 + q * 4);
            *(float4*)(sW + n * WP + q * 4) = v;
        }
        __syncthreads();
#pragma unroll
        for (int k8 = 0; k8 < 8; k8++) {
            const int kl = k8 * 8;
            uint32_t a[2][4];
#pragma unroll
            for (int mt = 0; mt < 2; mt++) {
                const float* ap = sXw + mt * (16 * XP) + h * 64 + kl;
                a[mt][0] = __float_as_uint(ap[0]);
                a[mt][1] = __float_as_uint(ap[8 * XP]);
                a[mt][2] = __float_as_uint(ap[4]);
                a[mt][3] = __float_as_uint(ap[8 * XP + 4]);
            }
#pragma unroll
            for (int nt = 0; nt < 8; nt++) {
                const float* bp = sWb + nt * (8 * WP) + kl;
                uint32_t b[2];
                b[0] = __float_as_uint(bp[0]);
                b[1] = __float_as_uint(bp[4]);
                mma_tf32(acc[0][nt], a[0], b);
                mma_tf32(acc[1][nt], a[1], b);
            }
        }
    }
}

__device__ __forceinline__ void zero_acc(float acc[2][8][4]) {
#pragma unroll
    for (int mt = 0; mt < 2; mt++)
#pragma unroll
        for (int nt = 0; nt < 8; nt++)
#pragma unroll
            for (int q = 0; q < 4; q++) acc[mt][nt][q] = 0.f;
}

__device__ __forceinline__ void store_acc(float* __restrict__ dst, int tid,
                                          const float acc[2][8][4]) {
    const int w = tid >> 5, lane = tid & 31;
    const int wm = w & 3, wn = w >> 2;
    const int lr = lane >> 2, lc = lane & 3;
    float* cx = dst + (wm * 32 + lr) * XP + wn * 64 + 2 * lc;
#pragma unroll
    for (int mt = 0; mt < 2; mt++)
#pragma unroll
        for (int nt = 0; nt < 8; nt++) {
            *(float2*)(cx + mt * (16 * XP) + nt * 8) =
                make_float2(acc[mt][nt][0], acc[mt][nt][1]);
            *(float2*)(cx + mt * (16 * XP) + 8 * XP + nt * 8) =
                make_float2(acc[mt][nt][2], acc[mt][nt][3]);
        }
}

// register epi1: sX = to_tf32(gelu(acc + sD[node(row)] + P[src(row)]))
__device__ __forceinline__ void epi1_reg(float* __restrict__ sX, int tid, int t128,
                                         const float acc[2][8][4],
                                         const float* __restrict__ Pbase,
                                         const int* __restrict__ sIdxT,
                                         const float* __restrict__ sD) {
    const int w = tid >> 5, lane = tid & 31;
    const int wm = w & 3, wn = w >> 2;
    const int lr = lane >> 2, lc = lane & 3;
#pragma unroll
    for (int mt = 0; mt < 2; mt++) {
#pragma unroll
        for (int hf = 0; hf < 2; hf++) {
            int r = wm * 32 + mt * 16 + lr + hf * 8;
            int src = sIdxT[r];
            int nl = (t128 + r) / KNB;
            const float* pr = Pbase + (size_t)src * H;
            const float* dn = sD + nl * H;
            float* xrow = sX + r * XP;
            const int ai = hf * 2;
#pragma unroll
            for (int nt = 0; nt < 8; nt++) {
                int col = wn * 64 + nt * 8 + 2 * lc;
                float2 p = *(const float2*)(pr + col);
                float2 d = *(const float2*)(dn + col);
                *(float2*)(xrow + col) =
                    make_float2(to_tf32(gelu_exact(acc[mt][nt][ai] + d.x + p.x)),
                                to_tf32(gelu_exact(acc[mt][nt][ai + 1] + d.y + p.y)));
            }
        }
    }
}

__device__ __forceinline__ void epi_bias_gelu(float* __restrict__ dst, int tid,
                                              const float acc[2][8][4],
                                              const float* __restrict__ bias) {
    const int w = tid >> 5, lane = tid & 31;
    const int wm = w & 3, wn = w >> 2;
    const int lr = lane >> 2, lc = lane & 3;
    float* cx = dst + (wm * 32 + lr) * XP + wn * 64 + 2 * lc;
#pragma unroll
    for (int nt = 0; nt < 8; nt++) {
        float2 bv = *(const float2*)(bias + wn * 64 + nt * 8 + 2 * lc);
#pragma unroll
        for (int mt = 0; mt < 2; mt++) {
            *(float2*)(cx + mt * (16 * XP) + nt * 8) =
                make_float2(to_tf32(gelu_exact(acc[mt][nt][0] + bv.x)),
                            to_tf32(gelu_exact(acc[mt][nt][1] + bv.y)));
            *(float2*)(cx + mt * (16 * XP) + 8 * XP + nt * 8) =
                make_float2(to_tf32(gelu_exact(acc[mt][nt][2] + bv.x)),
                            to_tf32(gelu_exact(acc[mt][nt][3] + bv.y)));
        }
    }
}

__device__ __forceinline__ void epi_mask_bias(float* __restrict__ dst, int tid,
                                              const float acc[2][8][4],
                                              const float* __restrict__ bias,
                                              const float* __restrict__ sMask) {
    const int w = tid >> 5, lane = tid & 31;
    const int wm = w & 3, wn = w >> 2;
    const int lr = lane >> 2, lc = lane & 3;
    float* cx = dst + (wm * 32 + lr) * XP + wn * 64 + 2 * lc;
#pragma unroll
    for (int mt = 0; mt < 2; mt++) {
        int r0 = wm * 32 + mt * 16 + lr;
        float mk0 = sMask[r0], mk8 = sMask[r0 + 8];
#pragma unroll
        for (int nt = 0; nt < 8; nt++) {
            float2 bv = *(const float2*)(bias + wn * 64 + nt * 8 + 2 * lc);
            *(float2*)(cx + mt * (16 * XP) + nt * 8) =
                make_float2(mk0 * (acc[mt][nt][0] + bv.x), mk0 * (acc[mt][nt][1] + bv.y));
            *(float2*)(cx + mt * (16 * XP) + 8 * XP + nt * 8) =
                make_float2(mk8 * (acc[mt][nt][2] + bv.x), mk8 * (acc[mt][nt][3] + bv.y));
        }
    }
}

__device__ __forceinline__ void epi_to_global(float* __restrict__ gdst, int p0, int tid,
                                              const float acc[2][8][4],
                                              const float* __restrict__ bias) {
    const int w = tid >> 5, lane = tid & 31;
    const int wm = w & 3, wn = w >> 2;
    const int lr = lane >> 2, lc = lane & 3;
#pragma unroll
    for (int nt = 0; nt < 8; nt++) {
        int col = wn * 64 + nt * 8 + 2 * lc;
        float2 bv = bias ? *(const float2*)(bias + col) : make_float2(0.f, 0.f);
#pragma unroll
        for (int mt = 0; mt < 2; mt++) {
            int r0 = wm * 32 + mt * 16 + lr;
            *(float2*)(gdst + (size_t)(p0 + r0) * H + col) =
                make_float2(acc[mt][nt][0] + bv.x, acc[mt][nt][1] + bv.y);
            *(float2*)(gdst + (size_t)(p0 + r0 + 8) * H + col) =
                make_float2(acc[mt][nt][2] + bv.x, acc[mt][nt][3] + bv.y);
        }
    }
}

// ---------------- prep weights ----------------
__global__ void prep_weights(const float* __restrict__ W1, const float* __restrict__ W2,
                             const float* __restrict__ W3, const float* __restrict__ W11,
                             const float* __restrict__ W12, const float* __restrict__ W13,
                             const float* __restrict__ W_in, const float* __restrict__ W_out) {
    int idx = blockIdx.x * 256 + threadIdx.x;
    if (idx >= 19 * HH) return;
    int m = idx / HH;
    int r = (idx >> 7) & 127;
    int c = idx & 127;
    float v;
    switch (m) {
        case W_E1:  v = W1[(128 + c) * H + r] + W1[(384 + c) * H + r]; break;
        case W_2T:  v = W2[c * H + r]; break;
        case W_3T:  v = W3[c * H + r]; break;
        case W_11E: v = W11[(128 + c) * H + r]; break;
        case W_12T: v = W12[c * H + r]; break;
        case W_13T: v = W13[c * H + r]; break;
        case W_1V:  v = W1[c * H + r]; break;
        case W_1G:  v = W1[(256 + c) * H + r]; break;
        case W_1A:  v = W1[(512 + c) * H + r]; break;
        case W_11V: v = W11[c * H + r]; break;
        case W_11G: v = W11[(256 + c) * H + r]; break;
        default:
            if (m < W_OUTT) {
                int nc = m - W_INT;
                v = W_in[c * 512 + nc * 128 + r];
            } else {
                int kc = m - W_OUTT;
                v = W_out[(kc * 128 + c) * H + r];
            }
            break;
    }
    g_Wt[idx] = to_tf32(v);
}

// ---------------- pre1 (grid 32x2) ----------------
__global__ void __launch_bounds__(256)
pre1_mma(const float* __restrict__ hV, const float* __restrict__ hVa,
         const float* __restrict__ b1) {
    extern __shared__ float smf[];
    float* sXa = smf;
    float* sXb = smf + 16896;
    float* sW  = smf + 33792;
    const int tid = threadIdx.x;
    const int p0 = blockIdx.x * 128;
    const int z = blockIdx.y;
    const int r = tid >> 1, ch = (tid & 1) * 64;

    {
        const float* a = hV + (size_t)(p0 + r) * H + ch;
        float* xa = sXa + r * XP + ch;
#pragma unroll
        for (int c = 0; c < 64; c += 4) {
            float4 v = *(const float4*)(a + c);
            xa[c] = to_tf32(v.x); xa[c+1] = to_tf32(v.y); xa[c+2] = to_tf32(v.z); xa[c+3] = to_tf32(v.w);
        }
        if (z == 1) {
            const float* b = hVa + (size_t)(p0 + r) * H + ch;
            float* xb = sXb + r * XP + ch;
#pragma unroll
            for (int c = 0; c < 64; c += 4) {
                float4 u = *(const float4*)(b + c);
                xb[c] = to_tf32(u.x); xb[c+1] = to_tf32(u.y); xb[c+2] = to_tf32(u.z); xb[c+3] = to_tf32(u.w);
            }
        }
    }

    float acc[2][8][4];
    zero_acc(acc);
    if (z == 0) {
        gemm256(sXa, sW, g_Wt + W_1V * HH, tid, acc);
        epi_to_global(g_D1, p0, tid, acc, b1);
    } else {
        gemm256(sXa, sW, g_Wt + W_1G * HH, tid, acc);
        gemm256(sXb, sW, g_Wt + W_1A * HH, tid, acc);
        epi_to_global(g_P1, p0, tid, acc, (const float*)nullptr);
    }
}

// ---------------- pre2 (grid 32x2) ----------------
__global__ void __launch_bounds__(256)
pre2_mma(const float* __restrict__ hVf, const float* __restrict__ b11) {
    extern __shared__ float smf[];
    float* sXa = smf;
    float* sW  = smf + 16896;
    const int tid = threadIdx.x;
    const int p0 = blockIdx.x * 128;
    const int z = blockIdx.y;
    const int r = tid >> 1, ch = (tid & 1) * 64;

    {
        const float* a = hVf + (size_t)(p0 + r) * H + ch;
        float* xa = sXa + r * XP + ch;
#pragma unroll
        for (int c = 0; c < 64; c += 4) {
            float4 v = *(const float4*)(a + c);
            xa[c] = to_tf32(v.x); xa[c+1] = to_tf32(v.y); xa[c+2] = to_tf32(v.z); xa[c+3] = to_tf32(v.w);
        }
    }

    float acc[2][8][4];
    zero_acc(acc);
    if (z == 0) {
        gemm256(sXa, sW, g_Wt + W_11V * HH, tid, acc);
        epi_to_global(g_D2, p0, tid, acc, b11);
    } else {
        gemm256(sXa, sW, g_Wt + W_11G * HH, tid, acc);
        epi_to_global(g_P2, p0, tid, acc, (const float*)nullptr);
    }
}

// node/edge smem layout (floats):
#define SMEM_MLP 28176

// ---------------- node message MLP + sum_K + LN1 ----------------
__global__ void __launch_bounds__(256, 2)
node_mma_kernel(const float* __restrict__ hV, const float* __restrict__ hE,
                const float* __restrict__ b2, const float* __restrict__ b3,
                const float* __restrict__ g1, const float* __restrict__ be1,
                const float* __restrict__ maskA, const int* __restrict__ Eidx) {
    extern __shared__ float smf[];
    float* sX    = smf;
    float* sW    = smf + 16896;
    float* sAcc2 = sW;
    float* sD    = smf + 25600;
    float* sAcc  = smf + 26624;
    int*   sIdx  = (int*)(smf + 27648);
    float* sMask = smf + 28032;
    float* sRed  = smf + 28160;

    const int tid = threadIdx.x;
    const int p0 = blockIdx.x * 8;
    const int bb = p0 >> 11;
    const int r = tid >> 1, ch = (tid & 1) * 64;
    const float* P1b = g_P1 + (size_t)bb * NN * H;

    for (int i = tid; i < 8 * H; i += 256) {
        sD[i] = g_D1[(size_t)p0 * H + i];
        sAcc[i] = 0.f;
    }
    for (int i = tid; i < 8 * KNB; i += 256) sIdx[i] = Eidx[(size_t)p0 * KNB + i];

    float acc[2][8][4];

    for (int t = 0; t < 3; t++) {
        const int e0 = p0 * KNB + t * 128;
        float* xr = sX + r * XP + ch;

        __syncthreads();
        {
            const float* a = hE + (size_t)(e0 + r) * H + ch;
#pragma unroll
            for (int c = 0; c < 64; c += 4) {
                float4 v = *(const float4*)(a + c);
                xr[c] = to_tf32(v.x); xr[c+1] = to_tf32(v.y);
                xr[c+2] = to_tf32(v.z); xr[c+3] = to_tf32(v.w);
            }
        }
        if (tid < 128) sMask[tid] = maskA[e0 + tid];

        // GEMM1 + register epi1
        zero_acc(acc);
        gemm256(sX, sW, g_Wt + W_E1 * HH, tid, acc);
        __syncthreads();
        epi1_reg(sX, tid, t * 128, acc, P1b, sIdx + t * 128, sD);

        // GEMM2 + register epi2
        zero_acc(acc);
        gemm256(sX, sW, g_Wt + W_2T * HH, tid, acc);
        __syncthreads();
        epi_bias_gelu(sX, tid, acc, b2);

        // GEMM3 + register epi3 (mask)
        zero_acc(acc);
        gemm256(sX, sW, g_Wt + W_3T * HH, tid, acc);
        __syncthreads();
        epi_mask_bias(sX, tid, acc, b3, sMask);
        for (int i = tid; i < 2048; i += 256) sAcc2[i] = 0.f;
        __syncthreads();

        // segment-sum rows -> per-node partials
        {
            const int col = tid & 127, half = tid >> 7;
            int rr = half * 64;
            int nl = (t * 128 + rr) / KNB;
            int nxt = (nl + 1) * KNB - t * 128;
            float a = 0.f;
            for (; rr < half * 64 + 64; rr++) {
                if (rr == nxt) { sAcc2[half * 1024 + nl * 128 + col] = a; nl++; nxt += KNB; a = 0.f; }
                a += sX[rr * XP + col];
            }
            sAcc2[half * 1024 + nl * 128 + col] = a;
        }
        __syncthreads();
        for (int i = tid; i < 1024; i += 256)
            sAcc[i] += sAcc2[i] + sAcc2[1024 + i];
    }
    __syncthreads();

    // LN1: 2 nodes at a time
    for (int step = 0; step < 4; step++) {
        const int g = tid >> 7;
        const int n = step * 2 + g;
        const int c = tid & 127;
        float u = hV[(size_t)(p0 + n) * H + c] + sAcc[n * 128 + c] * (1.0f / 30.0f);
        float s = u;
#pragma unroll
        for (int off = 16; off > 0; off >>= 1) s += __shfl_xor_sync(0xffffffffu, s, off);
        if ((tid & 31) == 0) sRed[tid >> 5] = s;
        __syncthreads();
        float mean = (sRed[g*4] + sRed[g*4+1] + sRed[g*4+2] + sRed[g*4+3]) * (1.0f / H);
        float d = u - mean;
        float v2 = d * d;
#pragma unroll
        for (int off = 16; off > 0; off >>= 1) v2 += __shfl_xor_sync(0xffffffffu, v2, off);
        if ((tid & 31) == 0) sRed[8 + (tid >> 5)] = v2;
        __syncthreads();
        float var = (sRed[8+g*4] + sRed[8+g*4+1] + sRed[8+g*4+2] + sRed[8+g*4+3]) * (1.0f / H);
        g_hV1[(size_t)(p0 + n) * H + c] = d * rsqrtf(var + 1e-5f) * g1[c] + be1[c];
        __syncthreads();
    }
}

// ---------------- edge update MLP + LN3 ----------------
__global__ void __launch_bounds__(256, 2)
edge_mma_kernel(const float* __restrict__ hE,
                const float* __restrict__ b12, const float* __restrict__ b13,
                const float* __restrict__ g3, const float* __restrict__ be3,
                const int* __restrict__ Eidx, float* __restrict__ outE) {
    extern __shared__ float smf[];
    float* sX   = smf;
    float* sW   = smf + 16896;
    float* sD   = smf + 25600;
    int*   sIdx = (int*)(smf + 27648);

    const int tid = threadIdx.x;
    const int w = tid >> 5, lane = tid & 31;
    const int p0 = blockIdx.x * 8;
    const int bb = p0 >> 11;
    const int r = tid >> 1, ch = (tid & 1) * 64;
    const float* P2b = g_P2 + (size_t)bb * NN * H;

    for (int i = tid; i < 8 * H; i += 256) sD[i] = g_D2[(size_t)p0 * H + i];
    for (int i = tid; i < 8 * KNB; i += 256) sIdx[i] = Eidx[(size_t)p0 * KNB + i];

    float b13v[4], g3v[4], be3v[4];
#pragma unroll
    for (int q = 0; q < 4; q++) {
        b13v[q] = b13[lane + 32 * q];
        g3v[q]  = g3[lane + 32 * q];
        be3v[q] = be3[lane + 32 * q];
    }

    float acc[2][8][4];

    for (int t = 0; t < 3; t++) {
        const int e0 = p0 * KNB + t * 128;
        float* xr = sX + r * XP + ch;
        const float* arow = hE + (size_t)(e0 + r) * H + ch;

        __syncthreads();
#pragma unroll
        for (int c = 0; c < 64; c += 4) {
            float4 v = *(const float4*)(arow + c);
            xr[c] = to_tf32(v.x); xr[c+1] = to_tf32(v.y);
            xr[c+2] = to_tf32(v.z); xr[c+3] = to_tf32(v.w);
        }

        zero_acc(acc);
        gemm256(sX, sW, g_Wt + W_11E * HH, tid, acc);
        __syncthreads();
        epi1_reg(sX, tid, t * 128, acc, P2b, sIdx + t * 128, sD);

        zero_acc(acc);
        gemm256(sX, sW, g_Wt + W_12T * HH, tid, acc);
        __syncthreads();
        epi_bias_gelu(sX, tid, acc, b12);

        zero_acc(acc);
        gemm256(sX, sW, g_Wt + W_13T * HH, tid, acc);
        __syncthreads();
        store_acc(sX, tid, acc);
        __syncthreads();

        // LN3 with fused b13 + hE residual: each warp 16 rows
        for (int rr = w * 16; rr < w * 16 + 16; rr++) {
            const float* he = hE + (size_t)(e0 + rr) * H;
            float v[4];
            float ssum = 0.f;
#pragma unroll
            for (int q = 0; q < 4; q++) {
                v[q] = sX[rr * XP + lane + 32 * q] + b13v[q] + he[lane + 32 * q];
                ssum += v[q];
            }
#pragma unroll
            for (int off = 16; off > 0; off >>= 1) ssum += __shfl_xor_sync(0xffffffffu, ssum, off);
            float mean = ssum * (1.0f / H);
            float vs = 0.f;
#pragma unroll
            for (int q = 0; q < 4; q++) { v[q] -= mean; vs += v[q] * v[q]; }
#pragma unroll
            for (int off = 16; off > 0; off >>= 1) vs += __shfl_xor_sync(0xffffffffu, vs, off);
            float rs = rsqrtf(vs * (1.0f / H) + 1e-5f);
#pragma unroll
            for (int q = 0; q < 4; q++)
                outE[(size_t)(e0 + rr) * H + lane + 32 * q] = v[q] * rs * g3v[q] + be3v[q];
        }
        __syncthreads();
    }
}

// ---------------- FFN (tensor): 128 nodes/CTA, grid 32 (R6 known-good form) ----------------
// smem: sXa 16896 | sXb 16896 | sW 8704 | sRedA 256
__global__ void __launch_bounds__(256)
ffn_mma(const float* __restrict__ b_in, const float* __restrict__ b_out,
        const float* __restrict__ g2, const float* __restrict__ be2,
        const float* __restrict__ maskV, float* __restrict__ outV) {
    extern __shared__ float smf[];
    float* sXa   = smf;
    float* sXb   = smf + 16896;
    float* sW    = smf + 33792;
    float* sRedA = smf + 42496;
    const int tid = threadIdx.x;
    const int p0 = blockIdx.x * 128;
    const int r = tid >> 1, ch = (tid & 1) * 64;

    {
        const float* a = g_hV1 + (size_t)(p0 + r) * H + ch;
        float* xa = sXa + r * XP + ch;
#pragma unroll
        for (int c = 0; c < 64; c += 4) {
            float4 v = *(const float4*)(a + c);
            xa[c] = to_tf32(v.x); xa[c+1] = to_tf32(v.y);
            xa[c+2] = to_tf32(v.z); xa[c+3] = to_tf32(v.w);
        }
    }

    float acc[2][8][4], acc2[2][8][4];
    zero_acc(acc2);
#pragma unroll
    for (int nc = 0; nc < 4; nc++) {
        zero_acc(acc);
        gemm256(sXa, sW, g_Wt + (W_INT + nc) * HH, tid, acc);
        __syncthreads();
        epi_bias_gelu(sXb, tid, acc, b_in + nc * 128);
        gemm256(sXb, sW, g_Wt + (W_OUTT + nc) * HH, tid, acc2);
    }
    __syncthreads();
    store_acc(sXb, tid, acc2);
    __syncthreads();

    // LN2 + maskV; residual from g_hV1 (fp32)
    float* xr = sXb + r * XP + ch;
    {
        const float* res = g_hV1 + (size_t)(p0 + r) * H + ch;
        float s = 0.f;
#pragma unroll
        for (int c = 0; c < 64; c += 4) {
            float4 x = *(float4*)(xr + c);
            float4 rv = *(const float4*)(res + c);
            float4 bo = *(const float4*)(b_out + ch + c);
            x.x += rv.x + bo.x; x.y += rv.y + bo.y;
            x.z += rv.z + bo.z; x.w += rv.w + bo.w;
            *(float4*)(xr + c) = x;
            s += x.x + x.y + x.z + x.w;
        }
        sRedA[tid] = s;
    }
    __syncthreads();
    float mean = (sRedA[tid] + sRedA[tid ^ 1]) * (1.0f / H);
    __syncthreads();
    {
        float v2 = 0.f;
#pragma unroll
        for (int c = 0; c < 64; c++) {
            float d = xr[c] - mean;
            v2 += d * d;
        }
        sRedA[tid] = v2;
    }
    __syncthreads();
    float var = (sRedA[tid] + sRedA[tid ^ 1]) * (1.0f / H);
    float rs = rsqrtf(var + 1e-5f);
    float mv = maskV[p0 + r];
#pragma unroll
    for (int c = 0; c < 64; c++) {
        int col = ch + c;
        outV[(size_t)(p0 + r) * H + col] =
            ((xr[c] - mean) * rs * g2[col] + be2[col]) * mv;
    }
}

// ---------------- launch ----------------
extern "C" void kernel_launch(void* const* d_in, const int* in_sizes, int n_in,
                              void* d_out, int out_size) {
    const float* hV    = (const float*)d_in[0];
    const float* hVa   = (const float*)d_in[1];
    const float* hE    = (const float*)d_in[2];
    const float* W1    = (const float*)d_in[3];
    const float* b1    = (const float*)d_in[4];
    const float* W2    = (const float*)d_in[5];
    const float* b2    = (const float*)d_in[6];
    const float* W3    = (const float*)d_in[7];
    const float* b3    = (const float*)d_in[8];
    const float* W11   = (const float*)d_in[9];
    const float* b11   = (const float*)d_in[10];
    const float* W12   = (const float*)d_in[11];
    const float* b12   = (const float*)d_in[12];
    const float* W13   = (const float*)d_in[13];
    const float* b13   = (const float*)d_in[14];
    const float* W_in  = (const float*)d_in[15];
    const float* b_in  = (const float*)d_in[16];
    const float* W_out = (const float*)d_in[17];
    const float* b_out = (const float*)d_in[18];
    const float* g1    = (const float*)d_in[19];
    const float* be1   = (const float*)d_in[20];
    const float* g2    = (const float*)d_in[21];
    const float* be2   = (const float*)d_in[22];
    const float* g3    = (const float*)d_in[23];
    const float* be3   = (const float*)d_in[24];
    const float* maskV = (const float*)d_in[25];
    const float* maskA = (const float*)d_in[26];
    const int*   Eidx  = (const int*)d_in[27];

    const int BN = in_sizes[0] / H;   // 4096
    float* outV = (float*)d_out;
    float* outE = (float*)d_out + (size_t)BN * H;

    const size_t smemMLP  = SMEM_MLP * sizeof(float);         // ~110.1 KB
    const size_t smemPRE1 = (33792 + 8704) * sizeof(float);   // 166 KB
    const size_t smemSML  = (16896 + 8704) * sizeof(float);   // 100 KB
    const size_t smemFFN  = (42496 + 256) * sizeof(float);    // 167 KB

    cudaFuncSetAttribute(node_mma_kernel, cudaFuncAttributeMaxDynamicSharedMemorySize, (int)smemMLP);
    cudaFuncSetAttribute(edge_mma_kernel, cudaFuncAttributeMaxDynamicSharedMemorySize, (int)smemMLP);
    cudaFuncSetAttribute(pre1_mma, cudaFuncAttributeMaxDynamicSharedMemorySize, (int)smemPRE1);
    cudaFuncSetAttribute(pre2_mma, cudaFuncAttributeMaxDynamicSharedMemorySize, (int)smemSML);
    cudaFuncSetAttribute(ffn_mma,  cudaFuncAttributeMaxDynamicSharedMemorySize, (int)smemFFN);

    prep_weights<<<(19 * HH + 255) / 256, 256>>>(W1, W2, W3, W11, W12, W13, W_in, W_out);
    pre1_mma<<<dim3(BN / 128, 2), 256, smemPRE1>>>(hV, hVa, b1);
    node_mma_kernel<<<BN / 8, 256, smemMLP>>>(hV, hE, b2, b3, g1, be1, maskA, Eidx);
    ffn_mma<<<BN / 128, 256, smemFFN>>>(b_in, b_out, g2, be2, maskV, outV);
    pre2_mma<<<dim3(BN / 128, 2), 256, smemSML>>>(outV, b11);
    edge_mma_kernel<<<BN / 8, 256, smemMLP>>>(hE, b12, b13, g3, be3, Eidx, outE);
}

// round 10
// speedup vs baseline: 3.3860x; 1.0858x over previous
#include <cuda_runtime.h>
#include <cstdint>
#include <math.h>

#define H      128
#define HH     (H * H)
#define KNB    48
#define NN     2048
#define BNTOT  4096
#define XP     132          // activation tile pitch (floats)
#define WP     68           // weight tile pitch (floats)

// weight matrix slots in g_Wt (all 128x128 [n][kperm], tf32-rounded)
#define W_E1   0
#define W_2T   1
#define W_3T   2
#define W_11E  3
#define W_12T  4
#define W_13T  5
#define W_1V   6
#define W_1G   7
#define W_1A   8
#define W_11V  9
#define W_11G  10
#define W_INT  11   // 11..14: W_in^T chunks
#define W_OUTT 15   // 15..18: W_out^T chunks

__device__ float g_Wt[19 * HH];
__device__ float g_D1[BNTOT * H];
__device__ float g_P1[BNTOT * H];
__device__ float g_D2[BNTOT * H];
__device__ float g_P2[BNTOT * H];
__device__ float g_hV1[BNTOT * H];

__device__ __forceinline__ float to_tf32(float x) {
    uint32_t u;
    asm("cvt.rna.tf32.f32 %0, %1;" : "=r"(u) : "f"(x));
    return __uint_as_float(u);
}

__device__ __forceinline__ float gelu_exact(float x) {
    return 0.5f * x * (1.0f + erff(x * 0.70710678118654752f));
}

__device__ __forceinline__ void mma_tf32(float d[4], const uint32_t a[4], const uint32_t b[2]) {
    asm volatile("mma.sync.aligned.m16n8k8.row.col.f32.tf32.tf32.f32 "
                 "{%0,%1,%2,%3}, {%4,%5,%6,%7}, {%8,%9}, {%0,%1,%2,%3};"
                 : "+f"(d[0]), "+f"(d[1]), "+f"(d[2]), "+f"(d[3])
                 : "r"(a[0]), "r"(a[1]), "r"(a[2]), "r"(a[3]), "r"(b[0]), "r"(b[1]));
}

// stage one 64-k half of a weight matrix (128n x 64k permuted floats) into sW
__device__ __forceinline__ void stage_W_half(float* __restrict__ sW,
                                             const float* __restrict__ Wg, int h, int tid) {
#pragma unroll
    for (int i = 0; i < 8; i++) {
        int idx = tid + 256 * i;
        int n = idx >> 4, q = idx & 15;
        float4 v = *(const float4*)(Wg + n * H + h * 64 + q * 4);
        *(float4*)(sW + n * WP + q * 4) = v;
    }
}

// ---------------- 128x128x128 tf32 GEMM, 256 threads (8 warps, 4m x 2n) ----------------
// B is k-pair-permuted: {W[n][k], W[n][k+4]} adjacent -> single float2 LDS.
__device__ __forceinline__ void gemm256(const float* __restrict__ sX, float* __restrict__ sW,
                                        const float* __restrict__ Wg, int tid,
                                        float acc[2][8][4]) {
    const int w = tid >> 5, lane = tid & 31;
    const int wm = w & 3, wn = w >> 2;
    const int lr = lane >> 2, lc = lane & 3;
    const float* sXw = sX + (wm * 32 + lr) * XP + lc;
    const float* sWb = sW + (wn * 64 + lr) * WP + 2 * lc;
#pragma unroll
    for (int h = 0; h < 2; h++) {
        __syncthreads();
        stage_W_half(sW, Wg, h, tid);
        __syncthreads();
#pragma unroll
        for (int k8 = 0; k8 < 8; k8++) {
            const int kl = k8 * 8;
            uint32_t a[2][4];
#pragma unroll
            for (int mt = 0; mt < 2; mt++) {
                const float* ap = sXw + mt * (16 * XP) + h * 64 + kl;
                a[mt][0] = __float_as_uint(ap[0]);
                a[mt][1] = __float_as_uint(ap[8 * XP]);
                a[mt][2] = __float_as_uint(ap[4]);
                a[mt][3] = __float_as_uint(ap[8 * XP + 4]);
            }
#pragma unroll
            for (int nt = 0; nt < 8; nt++) {
                float2 bv = *(const float2*)(sWb + nt * (8 * WP) + kl);
                uint32_t b[2] = {__float_as_uint(bv.x), __float_as_uint(bv.y)};
                mma_tf32(acc[0][nt], a[0], b);
                mma_tf32(acc[1][nt], a[1], b);
            }
        }
    }
}

// ---------------- 32x128x128 tf32 GEMM, 256 threads (8 warps across n) ----------------
__device__ __forceinline__ void gemm32(const float* __restrict__ sX, float* __restrict__ sW,
                                       const float* __restrict__ Wg, int tid,
                                       float acc[2][2][4]) {
    const int w = tid >> 5, lane = tid & 31;
    const int lr = lane >> 2, lc = lane & 3;
    const float* sXw = sX + lr * XP + lc;
    const float* sWb = sW + (w * 16 + lr) * WP + 2 * lc;
#pragma unroll
    for (int h = 0; h < 2; h++) {
        __syncthreads();
        stage_W_half(sW, Wg, h, tid);
        __syncthreads();
#pragma unroll
        for (int k8 = 0; k8 < 8; k8++) {
            const int kl = k8 * 8;
            uint32_t a[2][4];
#pragma unroll
            for (int mt = 0; mt < 2; mt++) {
                const float* ap = sXw + mt * (16 * XP) + h * 64 + kl;
                a[mt][0] = __float_as_uint(ap[0]);
                a[mt][1] = __float_as_uint(ap[8 * XP]);
                a[mt][2] = __float_as_uint(ap[4]);
                a[mt][3] = __float_as_uint(ap[8 * XP + 4]);
            }
#pragma unroll
            for (int nt = 0; nt < 2; nt++) {
                float2 bv = *(const float2*)(sWb + nt * (8 * WP) + kl);
                uint32_t b[2] = {__float_as_uint(bv.x), __float_as_uint(bv.y)};
                mma_tf32(acc[0][nt], a[0], b);
                mma_tf32(acc[1][nt], a[1], b);
            }
        }
    }
}

__device__ __forceinline__ void zero_acc(float acc[2][8][4]) {
#pragma unroll
    for (int mt = 0; mt < 2; mt++)
#pragma unroll
        for (int nt = 0; nt < 8; nt++)
#pragma unroll
            for (int q = 0; q < 4; q++) acc[mt][nt][q] = 0.f;
}

__device__ __forceinline__ void zero_acc32(float acc[2][2][4]) {
#pragma unroll
    for (int mt = 0; mt < 2; mt++)
#pragma unroll
        for (int nt = 0; nt < 2; nt++)
#pragma unroll
            for (int q = 0; q < 4; q++) acc[mt][nt][q] = 0.f;
}

__device__ __forceinline__ void store_acc(float* __restrict__ dst, int tid,
                                          const float acc[2][8][4]) {
    const int w = tid >> 5, lane = tid & 31;
    const int wm = w & 3, wn = w >> 2;
    const int lr = lane >> 2, lc = lane & 3;
    float* cx = dst + (wm * 32 + lr) * XP + wn * 64 + 2 * lc;
#pragma unroll
    for (int mt = 0; mt < 2; mt++)
#pragma unroll
        for (int nt = 0; nt < 8; nt++) {
            *(float2*)(cx + mt * (16 * XP) + nt * 8) =
                make_float2(acc[mt][nt][0], acc[mt][nt][1]);
            *(float2*)(cx + mt * (16 * XP) + 8 * XP + nt * 8) =
                make_float2(acc[mt][nt][2], acc[mt][nt][3]);
        }
}

// register epi1: sX = to_tf32(gelu(acc + sD[node(row)] + P[src(row)]))
__device__ __forceinline__ void epi1_reg(float* __restrict__ sX, int tid, int t128,
                                         const float acc[2][8][4],
                                         const float* __restrict__ Pbase,
                                         const int* __restrict__ sIdxT,
                                         const float* __restrict__ sD) {
    const int w = tid >> 5, lane = tid & 31;
    const int wm = w & 3, wn = w >> 2;
    const int lr = lane >> 2, lc = lane & 3;
#pragma unroll
    for (int mt = 0; mt < 2; mt++) {
#pragma unroll
        for (int hf = 0; hf < 2; hf++) {
            int r = wm * 32 + mt * 16 + lr + hf * 8;
            int src = sIdxT[r];
            int nl = (t128 + r) / KNB;
            const float* pr = Pbase + (size_t)src * H;
            const float* dn = sD + nl * H;
            float* xrow = sX + r * XP;
            const int ai = hf * 2;
#pragma unroll
            for (int nt = 0; nt < 8; nt++) {
                int col = wn * 64 + nt * 8 + 2 * lc;
                float2 p = *(const float2*)(pr + col);
                float2 d = *(const float2*)(dn + col);
                *(float2*)(xrow + col) =
                    make_float2(to_tf32(gelu_exact(acc[mt][nt][ai] + d.x + p.x)),
                                to_tf32(gelu_exact(acc[mt][nt][ai + 1] + d.y + p.y)));
            }
        }
    }
}

__device__ __forceinline__ void epi_bias_gelu(float* __restrict__ dst, int tid,
                                              const float acc[2][8][4],
                                              const float* __restrict__ bias) {
    const int w = tid >> 5, lane = tid & 31;
    const int wm = w & 3, wn = w >> 2;
    const int lr = lane >> 2, lc = lane & 3;
    float* cx = dst + (wm * 32 + lr) * XP + wn * 64 + 2 * lc;
#pragma unroll
    for (int nt = 0; nt < 8; nt++) {
        float2 bv = *(const float2*)(bias + wn * 64 + nt * 8 + 2 * lc);
#pragma unroll
        for (int mt = 0; mt < 2; mt++) {
            *(float2*)(cx + mt * (16 * XP) + nt * 8) =
                make_float2(to_tf32(gelu_exact(acc[mt][nt][0] + bv.x)),
                            to_tf32(gelu_exact(acc[mt][nt][1] + bv.y)));
            *(float2*)(cx + mt * (16 * XP) + 8 * XP + nt * 8) =
                make_float2(to_tf32(gelu_exact(acc[mt][nt][2] + bv.x)),
                            to_tf32(gelu_exact(acc[mt][nt][3] + bv.y)));
        }
    }
}

__device__ __forceinline__ void epi_bias_gelu32(float* __restrict__ dst, int tid,
                                                const float acc[2][2][4],
                                                const float* __restrict__ bias) {
    const int w = tid >> 5, lane = tid & 31;
    const int lr = lane >> 2, lc = lane & 3;
    float* cx = dst + lr * XP + w * 16 + 2 * lc;
#pragma unroll
    for (int nt = 0; nt < 2; nt++) {
        float2 bv = *(const float2*)(bias + w * 16 + nt * 8 + 2 * lc);
#pragma unroll
        for (int mt = 0; mt < 2; mt++) {
            *(float2*)(cx + mt * (16 * XP) + nt * 8) =
                make_float2(to_tf32(gelu_exact(acc[mt][nt][0] + bv.x)),
                            to_tf32(gelu_exact(acc[mt][nt][1] + bv.y)));
            *(float2*)(cx + mt * (16 * XP) + 8 * XP + nt * 8) =
                make_float2(to_tf32(gelu_exact(acc[mt][nt][2] + bv.x)),
                            to_tf32(gelu_exact(acc[mt][nt][3] + bv.y)));
        }
    }
}

__device__ __forceinline__ void store_acc32(float* __restrict__ dst, int tid,
                                            const float acc[2][2][4]) {
    const int w = tid >> 5, lane = tid & 31;
    const int lr = lane >> 2, lc = lane & 3;
    float* cx = dst + lr * XP + w * 16 + 2 * lc;
#pragma unroll
    for (int mt = 0; mt < 2; mt++)
#pragma unroll
        for (int nt = 0; nt < 2; nt++) {
            *(float2*)(cx + mt * (16 * XP) + nt * 8) =
                make_float2(acc[mt][nt][0], acc[mt][nt][1]);
            *(float2*)(cx + mt * (16 * XP) + 8 * XP + nt * 8) =
                make_float2(acc[mt][nt][2], acc[mt][nt][3]);
        }
}

__device__ __forceinline__ void epi_mask_bias(float* __restrict__ dst, int tid,
                                              const float acc[2][8][4],
                                              const float* __restrict__ bias,
                                              const float* __restrict__ sMask) {
    const int w = tid >> 5, lane = tid & 31;
    const int wm = w & 3, wn = w >> 2;
    const int lr = lane >> 2, lc = lane & 3;
    float* cx = dst + (wm * 32 + lr) * XP + wn * 64 + 2 * lc;
#pragma unroll
    for (int mt = 0; mt < 2; mt++) {
        int r0 = wm * 32 + mt * 16 + lr;
        float mk0 = sMask[r0], mk8 = sMask[r0 + 8];
#pragma unroll
        for (int nt = 0; nt < 8; nt++) {
            float2 bv = *(const float2*)(bias + wn * 64 + nt * 8 + 2 * lc);
            *(float2*)(cx + mt * (16 * XP) + nt * 8) =
                make_float2(mk0 * (acc[mt][nt][0] + bv.x), mk0 * (acc[mt][nt][1] + bv.y));
            *(float2*)(cx + mt * (16 * XP) + 8 * XP + nt * 8) =
                make_float2(mk8 * (acc[mt][nt][2] + bv.x), mk8 * (acc[mt][nt][3] + bv.y));
        }
    }
}

__device__ __forceinline__ void epi_to_global(float* __restrict__ gdst, int p0, int tid,
                                              const float acc[2][8][4],
                                              const float* __restrict__ bias) {
    const int w = tid >> 5, lane = tid & 31;
    const int wm = w & 3, wn = w >> 2;
    const int lr = lane >> 2, lc = lane & 3;
#pragma unroll
    for (int nt = 0; nt < 8; nt++) {
        int col = wn * 64 + nt * 8 + 2 * lc;
        float2 bv = bias ? *(const float2*)(bias + col) : make_float2(0.f, 0.f);
#pragma unroll
        for (int mt = 0; mt < 2; mt++) {
            int r0 = wm * 32 + mt * 16 + lr;
            *(float2*)(gdst + (size_t)(p0 + r0) * H + col) =
                make_float2(acc[mt][nt][0] + bv.x, acc[mt][nt][1] + bv.y);
            *(float2*)(gdst + (size_t)(p0 + r0 + 8) * H + col) =
                make_float2(acc[mt][nt][2] + bv.x, acc[mt][nt][3] + bv.y);
        }
    }
}

// ---------------- prep weights: transpose/fold + tf32 + k-pair permutation ----------------
// kperm: within each 8-k group, (k, k+4) pairs stored adjacently -> B frags are float2.
__global__ void prep_weights(const float* __restrict__ W1, const float* __restrict__ W2,
                             const float* __restrict__ W3, const float* __restrict__ W11,
                             const float* __restrict__ W12, const float* __restrict__ W13,
                             const float* __restrict__ W_in, const float* __restrict__ W_out) {
    int idx = blockIdx.x * 256 + threadIdx.x;
    if (idx >= 19 * HH) return;
    int m = idx / HH;
    int r = (idx >> 7) & 127;
    int c = idx & 127;
    float v;
    switch (m) {
        case W_E1:  v = W1[(128 + c) * H + r] + W1[(384 + c) * H + r]; break;
        case W_2T:  v = W2[c * H + r]; break;
        case W_3T:  v = W3[c * H + r]; break;
        case W_11E: v = W11[(128 + c) * H + r]; break;
        case W_12T: v = W12[c * H + r]; break;
        case W_13T: v = W13[c * H + r]; break;
        case W_1V:  v = W1[c * H + r]; break;
        case W_1G:  v = W1[(256 + c) * H + r]; break;
        case W_1A:  v = W1[(512 + c) * H + r]; break;
        case W_11V: v = W11[c * H + r]; break;
        case W_11G: v = W11[(256 + c) * H + r]; break;
        default:
            if (m < W_OUTT) {
                int nc = m - W_INT;
                v = W_in[c * 512 + nc * 128 + r];
            } else {
                int kc = m - W_OUTT;
                v = W_out[(kc * 128 + c) * H + r];
            }
            break;
    }
    int kperm = (c & ~7) | ((c & 3) << 1) | ((c >> 2) & 1);
    g_Wt[m * HH + r * H + kperm] = to_tf32(v);
}

// ---------------- pre1 (grid 32x2) ----------------
__global__ void __launch_bounds__(256)
pre1_mma(const float* __restrict__ hV, const float* __restrict__ hVa,
         const float* __restrict__ b1) {
    extern __shared__ float smf[];
    float* sXa = smf;
    float* sXb = smf + 16896;
    float* sW  = smf + 33792;
    const int tid = threadIdx.x;
    const int p0 = blockIdx.x * 128;
    const int z = blockIdx.y;
    const int r = tid >> 1, ch = (tid & 1) * 64;

    {
        const float* a = hV + (size_t)(p0 + r) * H + ch;
        float* xa = sXa + r * XP + ch;
#pragma unroll
        for (int c = 0; c < 64; c += 4) {
            float4 v = *(const float4*)(a + c);
            xa[c] = to_tf32(v.x); xa[c+1] = to_tf32(v.y); xa[c+2] = to_tf32(v.z); xa[c+3] = to_tf32(v.w);
        }
        if (z == 1) {
            const float* b = hVa + (size_t)(p0 + r) * H + ch;
            float* xb = sXb + r * XP + ch;
#pragma unroll
            for (int c = 0; c < 64; c += 4) {
                float4 u = *(const float4*)(b + c);
                xb[c] = to_tf32(u.x); xb[c+1] = to_tf32(u.y); xb[c+2] = to_tf32(u.z); xb[c+3] = to_tf32(u.w);
            }
        }
    }

    float acc[2][8][4];
    zero_acc(acc);
    if (z == 0) {
        gemm256(sXa, sW, g_Wt + W_1V * HH, tid, acc);
        epi_to_global(g_D1, p0, tid, acc, b1);
    } else {
        gemm256(sXa, sW, g_Wt + W_1G * HH, tid, acc);
        gemm256(sXb, sW, g_Wt + W_1A * HH, tid, acc);
        epi_to_global(g_P1, p0, tid, acc, (const float*)nullptr);
    }
}

// ---------------- pre2 (grid 32x2) ----------------
__global__ void __launch_bounds__(256)
pre2_mma(const float* __restrict__ hVf, const float* __restrict__ b11) {
    extern __shared__ float smf[];
    float* sXa = smf;
    float* sW  = smf + 16896;
    const int tid = threadIdx.x;
    const int p0 = blockIdx.x * 128;
    const int z = blockIdx.y;
    const int r = tid >> 1, ch = (tid & 1) * 64;

    {
        const float* a = hVf + (size_t)(p0 + r) * H + ch;
        float* xa = sXa + r * XP + ch;
#pragma unroll
        for (int c = 0; c < 64; c += 4) {
            float4 v = *(const float4*)(a + c);
            xa[c] = to_tf32(v.x); xa[c+1] = to_tf32(v.y); xa[c+2] = to_tf32(v.z); xa[c+3] = to_tf32(v.w);
        }
    }

    float acc[2][8][4];
    zero_acc(acc);
    if (z == 0) {
        gemm256(sXa, sW, g_Wt + W_11V * HH, tid, acc);
        epi_to_global(g_D2, p0, tid, acc, b11);
    } else {
        gemm256(sXa, sW, g_Wt + W_11G * HH, tid, acc);
        epi_to_global(g_P2, p0, tid, acc, (const float*)nullptr);
    }
}

// node/edge smem layout (floats):
#define SMEM_MLP 28176

// ---------------- node message MLP + sum_K + LN1 ----------------
__global__ void __launch_bounds__(256, 2)
node_mma_kernel(const float* __restrict__ hV, const float* __restrict__ hE,
                const float* __restrict__ b2, const float* __restrict__ b3,
                const float* __restrict__ g1, const float* __restrict__ be1,
                const float* __restrict__ maskA, const int* __restrict__ Eidx) {
    extern __shared__ float smf[];
    float* sX    = smf;
    float* sW    = smf + 16896;
    float* sAcc2 = sW;
    float* sD    = smf + 25600;
    float* sAcc  = smf + 26624;
    int*   sIdx  = (int*)(smf + 27648);
    float* sMask = smf + 28032;
    float* sRed  = smf + 28160;

    const int tid = threadIdx.x;
    const int p0 = blockIdx.x * 8;
    const int bb = p0 >> 11;
    const int r = tid >> 1, ch = (tid & 1) * 64;
    const float* P1b = g_P1 + (size_t)bb * NN * H;

    for (int i = tid; i < 8 * H; i += 256) {
        sD[i] = g_D1[(size_t)p0 * H + i];
        sAcc[i] = 0.f;
    }
    for (int i = tid; i < 8 * KNB; i += 256) sIdx[i] = Eidx[(size_t)p0 * KNB + i];

    float acc[2][8][4];

    for (int t = 0; t < 3; t++) {
        const int e0 = p0 * KNB + t * 128;
        float* xr = sX + r * XP + ch;

        __syncthreads();
        {
            const float* a = hE + (size_t)(e0 + r) * H + ch;
#pragma unroll
            for (int c = 0; c < 64; c += 4) {
                float4 v = *(const float4*)(a + c);
                xr[c] = to_tf32(v.x); xr[c+1] = to_tf32(v.y);
                xr[c+2] = to_tf32(v.z); xr[c+3] = to_tf32(v.w);
            }
        }
        if (tid < 128) sMask[tid] = maskA[e0 + tid];

        // GEMM1 + register epi1
        zero_acc(acc);
        gemm256(sX, sW, g_Wt + W_E1 * HH, tid, acc);
        __syncthreads();
        epi1_reg(sX, tid, t * 128, acc, P1b, sIdx + t * 128, sD);

        // GEMM2 + register epi2
        zero_acc(acc);
        gemm256(sX, sW, g_Wt + W_2T * HH, tid, acc);
        __syncthreads();
        epi_bias_gelu(sX, tid, acc, b2);

        // GEMM3 + register epi3 (mask)
        zero_acc(acc);
        gemm256(sX, sW, g_Wt + W_3T * HH, tid, acc);
        __syncthreads();
        epi_mask_bias(sX, tid, acc, b3, sMask);
        for (int i = tid; i < 2048; i += 256) sAcc2[i] = 0.f;
        __syncthreads();

        // segment-sum rows -> per-node partials
        {
            const int col = tid & 127, half = tid >> 7;
            int rr = half * 64;
            int nl = (t * 128 + rr) / KNB;
            int nxt = (nl + 1) * KNB - t * 128;
            float a = 0.f;
            for (; rr < half * 64 + 64; rr++) {
                if (rr == nxt) { sAcc2[half * 1024 + nl * 128 + col] = a; nl++; nxt += KNB; a = 0.f; }
                a += sX[rr * XP + col];
            }
            sAcc2[half * 1024 + nl * 128 + col] = a;
        }
        __syncthreads();
        for (int i = tid; i < 1024; i += 256)
            sAcc[i] += sAcc2[i] + sAcc2[1024 + i];
    }
    __syncthreads();

    // LN1: 2 nodes at a time
    for (int step = 0; step < 4; step++) {
        const int g = tid >> 7;
        const int n = step * 2 + g;
        const int c = tid & 127;
        float u = hV[(size_t)(p0 + n) * H + c] + sAcc[n * 128 + c] * (1.0f / 30.0f);
        float s = u;
#pragma unroll
        for (int off = 16; off > 0; off >>= 1) s += __shfl_xor_sync(0xffffffffu, s, off);
        if ((tid & 31) == 0) sRed[tid >> 5] = s;
        __syncthreads();
        float mean = (sRed[g*4] + sRed[g*4+1] + sRed[g*4+2] + sRed[g*4+3]) * (1.0f / H);
        float d = u - mean;
        float v2 = d * d;
#pragma unroll
        for (int off = 16; off > 0; off >>= 1) v2 += __shfl_xor_sync(0xffffffffu, v2, off);
        if ((tid & 31) == 0) sRed[8 + (tid >> 5)] = v2;
        __syncthreads();
        float var = (sRed[8+g*4] + sRed[8+g*4+1] + sRed[8+g*4+2] + sRed[8+g*4+3]) * (1.0f / H);
        g_hV1[(size_t)(p0 + n) * H + c] = d * rsqrtf(var + 1e-5f) * g1[c] + be1[c];
        __syncthreads();
    }
}

// ---------------- edge update MLP + LN3 ----------------
__global__ void __launch_bounds__(256, 2)
edge_mma_kernel(const float* __restrict__ hE,
                const float* __restrict__ b12, const float* __restrict__ b13,
                const float* __restrict__ g3, const float* __restrict__ be3,
                const int* __restrict__ Eidx, float* __restrict__ outE) {
    extern __shared__ float smf[];
    float* sX   = smf;
    float* sW   = smf + 16896;
    float* sD   = smf + 25600;
    int*   sIdx = (int*)(smf + 27648);

    const int tid = threadIdx.x;
    const int w = tid >> 5, lane = tid & 31;
    const int p0 = blockIdx.x * 8;
    const int bb = p0 >> 11;
    const int r = tid >> 1, ch = (tid & 1) * 64;
    const float* P2b = g_P2 + (size_t)bb * NN * H;

    for (int i = tid; i < 8 * H; i += 256) sD[i] = g_D2[(size_t)p0 * H + i];
    for (int i = tid; i < 8 * KNB; i += 256) sIdx[i] = Eidx[(size_t)p0 * KNB + i];

    float b13v[4], g3v[4], be3v[4];
#pragma unroll
    for (int q = 0; q < 4; q++) {
        b13v[q] = b13[lane + 32 * q];
        g3v[q]  = g3[lane + 32 * q];
        be3v[q] = be3[lane + 32 * q];
    }

    float acc[2][8][4];

    for (int t = 0; t < 3; t++) {
        const int e0 = p0 * KNB + t * 128;
        float* xr = sX + r * XP + ch;
        const float* arow = hE + (size_t)(e0 + r) * H + ch;

        __syncthreads();
#pragma unroll
        for (int c = 0; c < 64; c += 4) {
            float4 v = *(const float4*)(arow + c);
            xr[c] = to_tf32(v.x); xr[c+1] = to_tf32(v.y);
            xr[c+2] = to_tf32(v.z); xr[c+3] = to_tf32(v.w);
        }

        zero_acc(acc);
        gemm256(sX, sW, g_Wt + W_11E * HH, tid, acc);
        __syncthreads();
        epi1_reg(sX, tid, t * 128, acc, P2b, sIdx + t * 128, sD);

        zero_acc(acc);
        gemm256(sX, sW, g_Wt + W_12T * HH, tid, acc);
        __syncthreads();
        epi_bias_gelu(sX, tid, acc, b12);

        zero_acc(acc);
        gemm256(sX, sW, g_Wt + W_13T * HH, tid, acc);
        __syncthreads();
        store_acc(sX, tid, acc);
        __syncthreads();

        // LN3 with fused b13 + hE residual: each warp 16 rows
        for (int rr = w * 16; rr < w * 16 + 16; rr++) {
            const float* he = hE + (size_t)(e0 + rr) * H;
            float v[4];
            float ssum = 0.f;
#pragma unroll
            for (int q = 0; q < 4; q++) {
                v[q] = sX[rr * XP + lane + 32 * q] + b13v[q] + he[lane + 32 * q];
                ssum += v[q];
            }
#pragma unroll
            for (int off = 16; off > 0; off >>= 1) ssum += __shfl_xor_sync(0xffffffffu, ssum, off);
            float mean = ssum * (1.0f / H);
            float vs = 0.f;
#pragma unroll
            for (int q = 0; q < 4; q++) { v[q] -= mean; vs += v[q] * v[q]; }
#pragma unroll
            for (int off = 16; off > 0; off >>= 1) vs += __shfl_xor_sync(0xffffffffu, vs, off);
            float rs = rsqrtf(vs * (1.0f / H) + 1e-5f);
#pragma unroll
            for (int q = 0; q < 4; q++)
                outE[(size_t)(e0 + rr) * H + lane + 32 * q] = v[q] * rs * g3v[q] + be3v[q];
        }
        __syncthreads();
    }
}

// ---------------- FFN (tensor): 32 nodes/CTA, grid 128 ----------------
// smem: sXa 32*132=4224 | sXb 4224 | sW 8704 -> 17152 floats (~68.6KB)
__global__ void __launch_bounds__(256)
ffn_mma(const float* __restrict__ b_in, const float* __restrict__ b_out,
        const float* __restrict__ g2, const float* __restrict__ be2,
        const float* __restrict__ maskV, float* __restrict__ outV) {
    extern __shared__ float smf[];
    float* sXa = smf;
    float* sXb = smf + 4224;
    float* sW  = smf + 8448;
    const int tid = threadIdx.x;
    const int w = tid >> 5, lane = tid & 31;
    const int p0 = blockIdx.x * 32;

    {
        const int r = tid >> 3, c0 = (tid & 7) * 16;
        const float* a = g_hV1 + (size_t)(p0 + r) * H + c0;
        float* xa = sXa + r * XP + c0;
#pragma unroll
        for (int c = 0; c < 16; c += 4) {
            float4 v = *(const float4*)(a + c);
            xa[c] = to_tf32(v.x); xa[c+1] = to_tf32(v.y);
            xa[c+2] = to_tf32(v.z); xa[c+3] = to_tf32(v.w);
        }
    }

    float acc[2][2][4], acc2[2][2][4];
    zero_acc32(acc2);
#pragma unroll
    for (int nc = 0; nc < 4; nc++) {
        zero_acc32(acc);
        gemm32(sXa, sW, g_Wt + (W_INT + nc) * HH, tid, acc);
        __syncthreads();
        epi_bias_gelu32(sXb, tid, acc, b_in + nc * 128);
        gemm32(sXb, sW, g_Wt + (W_OUTT + nc) * HH, tid, acc2);
    }
    __syncthreads();
    store_acc32(sXb, tid, acc2);
    __syncthreads();

    // LN2 + maskV: each warp handles 4 rows
    for (int rr = w * 4; rr < w * 4 + 4; rr++) {
        const size_t row = p0 + rr;
        const float* res = g_hV1 + row * H;
        float u[4];
        float s = 0.f;
#pragma unroll
        for (int q = 0; q < 4; q++) {
            int c = lane + 32 * q;
            u[q] = sXb[rr * XP + c] + res[c] + b_out[c];
            s += u[q];
        }
#pragma unroll
        for (int off = 16; off > 0; off >>= 1) s += __shfl_xor_sync(0xffffffffu, s, off);
        float mean = s * (1.0f / H);
        float vs = 0.f;
#pragma unroll
        for (int q = 0; q < 4; q++) { u[q] -= mean; vs += u[q] * u[q]; }
#pragma unroll
        for (int off = 16; off > 0; off >>= 1) vs += __shfl_xor_sync(0xffffffffu, vs, off);
        float rs = rsqrtf(vs * (1.0f / H) + 1e-5f);
        float mv = maskV[row];
#pragma unroll
        for (int q = 0; q < 4; q++) {
            int c = lane + 32 * q;
            outV[row * H + c] = (u[q] * rs * g2[c] + be2[c]) * mv;
        }
    }
}

// ---------------- launch ----------------
extern "C" void kernel_launch(void* const* d_in, const int* in_sizes, int n_in,
                              void* d_out, int out_size) {
    const float* hV    = (const float*)d_in[0];
    const float* hVa   = (const float*)d_in[1];
    const float* hE    = (const float*)d_in[2];
    const float* W1    = (const float*)d_in[3];
    const float* b1    = (const float*)d_in[4];
    const float* W2    = (const float*)d_in[5];
    const float* b2    = (const float*)d_in[6];
    const float* W3    = (const float*)d_in[7];
    const float* b3    = (const float*)d_in[8];
    const float* W11   = (const float*)d_in[9];
    const float* b11   = (const float*)d_in[10];
    const float* W12   = (const float*)d_in[11];
    const float* b12   = (const float*)d_in[12];
    const float* W13   = (const float*)d_in[13];
    const float* b13   = (const float*)d_in[14];
    const float* W_in  = (const float*)d_in[15];
    const float* b_in  = (const float*)d_in[16];
    const float* W_out = (const float*)d_in[17];
    const float* b_out = (const float*)d_in[18];
    const float* g1    = (const float*)d_in[19];
    const float* be1   = (const float*)d_in[20];
    const float* g2    = (const float*)d_in[21];
    const float* be2   = (const float*)d_in[22];
    const float* g3    = (const float*)d_in[23];
    const float* be3   = (const float*)d_in[24];
    const float* maskV = (const float*)d_in[25];
    const float* maskA = (const float*)d_in[26];
    const int*   Eidx  = (const int*)d_in[27];

    const int BN = in_sizes[0] / H;   // 4096
    float* outV = (float*)d_out;
    float* outE = (float*)d_out + (size_t)BN * H;

    const size_t smemMLP  = SMEM_MLP * sizeof(float);         // ~110.1 KB
    const size_t smemPRE1 = (33792 + 8704) * sizeof(float);   // 166 KB
    const size_t smemSML  = (16896 + 8704) * sizeof(float);   // 100 KB
    const size_t smemFFN  = 17152 * sizeof(float);            // 68.6 KB

    cudaFuncSetAttribute(node_mma_kernel, cudaFuncAttributeMaxDynamicSharedMemorySize, (int)smemMLP);
    cudaFuncSetAttribute(edge_mma_kernel, cudaFuncAttributeMaxDynamicSharedMemorySize, (int)smemMLP);
    cudaFuncSetAttribute(pre1_mma, cudaFuncAttributeMaxDynamicSharedMemorySize, (int)smemPRE1);
    cudaFuncSetAttribute(pre2_mma, cudaFuncAttributeMaxDynamicSharedMemorySize, (int)smemSML);
    cudaFuncSetAttribute(ffn_mma,  cudaFuncAttributeMaxDynamicSharedMemorySize, (int)smemFFN);

    prep_weights<<<(19 * HH + 255) / 256, 256>>>(W1, W2, W3, W11, W12, W13, W_in, W_out);
    pre1_mma<<<dim3(BN / 128, 2), 256, smemPRE1>>>(hV, hVa, b1);
    node_mma_kernel<<<BN / 8, 256, smemMLP>>>(hV, hE, b2, b3, g1, be1, maskA, Eidx);
    ffn_mma<<<BN / 32, 256, smemFFN>>>(b_in, b_out, g2, be2, maskV, outV);
    pre2_mma<<<dim3(BN / 128, 2), 256, smemSML>>>(outV, b11);
    edge_mma_kernel<<<BN / 8, 256, smemMLP>>>(hE, b12, b13, g3, be3, Eidx, outE);
}